// round 1
// baseline (speedup 1.0000x reference)
#include <cuda_runtime.h>
#include <math.h>

#define NN   100000
#define NE   1600000
#define CIN  256
#define HID  128
#define COUT 16

// Scratch (allocation-free rule: __device__ globals)
__device__ float g_hs[(size_t)NN * HID];    // h * dinv[src]  (pre-scaled messages)
__device__ float g_agg[(size_t)NN * HID];   // aggregation accumulator
__device__ int   g_deg[NN];
__device__ float g_dinv[NN];
__device__ int   g_is64;

// ---------------------------------------------------------------------------
// K0: init degrees (self-loop => 1) and sniff edge_index dtype (int64 vs int32)
// ---------------------------------------------------------------------------
__global__ void k_init(const int* __restrict__ e32) {
    int i = blockIdx.x * blockDim.x + threadIdx.x;
    if (i < NN) g_deg[i] = 1;
    if (i == 0) {
        // If data is little-endian int64 of values < 2^31, every odd int32 is 0.
        int is64 = 1;
        #pragma unroll 1
        for (int j = 0; j < 64; j++) {
            if (e32[2 * j + 1] != 0) { is64 = 0; break; }
        }
        g_is64 = is64;
    }
}

// ---------------------------------------------------------------------------
// K1: in-degree via int atomics
// ---------------------------------------------------------------------------
__global__ void k_deg(const void* __restrict__ eptr) {
    const long long* e64 = (const long long*)eptr;
    const int*       e32 = (const int*)eptr;
    const int is64 = g_is64;
    for (int e = blockIdx.x * blockDim.x + threadIdx.x; e < NE;
         e += gridDim.x * blockDim.x) {
        int d = is64 ? (int)e64[NE + e] : e32[NE + e];
        atomicAdd(&g_deg[d], 1);
    }
}

// ---------------------------------------------------------------------------
// K2: dinv = rsqrt(deg)
// ---------------------------------------------------------------------------
__global__ void k_dinv() {
    int i = blockIdx.x * blockDim.x + threadIdx.x;
    if (i < NN) g_dinv[i] = rsqrtf((float)g_deg[i]);
}

// ---------------------------------------------------------------------------
// K3: h = x @ W_conv  (fp32 tiled GEMM, BM=64, BN=128, BK=32, 256 threads)
// Epilogue: hs = h*dinv[node];  agg = b_conv + hs*dinv[node] (self-loop + bias)
// ---------------------------------------------------------------------------
__global__ __launch_bounds__(256) void k_gemm(const float* __restrict__ x,
                                              const float* __restrict__ W,
                                              const float* __restrict__ bc) {
    __shared__ float xs[32][64 + 4];   // transposed x tile, row = 68 floats (272B, 16B-aligned rows)
    __shared__ float ws[32][128];      // W tile

    const int tid  = threadIdx.x;
    const int row0 = blockIdx.x * 64;
    const int c0   = (tid & 31) * 4;   // output column group (0..124)
    const int r0   = (tid >> 5) * 8;   // output row group within tile (0..56)

    float acc[8][4];
    #pragma unroll
    for (int i = 0; i < 8; i++)
        #pragma unroll
        for (int j = 0; j < 4; j++) acc[i][j] = 0.f;

    const float4* x4 = (const float4*)x;
    const float4* W4 = (const float4*)W;

    for (int kt = 0; kt < CIN; kt += 32) {
        // load x tile [64 rows x 32 k] (8 consecutive threads fetch one row's 128B)
        #pragma unroll
        for (int i = 0; i < 2; i++) {
            int idx = i * 256 + tid;           // 0..511
            int r   = idx >> 3;                // 0..63
            int kq  = idx & 7;                 // 0..7 (float4 index in k)
            int node = row0 + r;
            float4 v = make_float4(0.f, 0.f, 0.f, 0.f);
            if (node < NN) v = x4[(size_t)node * (CIN / 4) + (kt >> 2) + kq];
            xs[kq * 4 + 0][r] = v.x;
            xs[kq * 4 + 1][r] = v.y;
            xs[kq * 4 + 2][r] = v.z;
            xs[kq * 4 + 3][r] = v.w;
        }
        // load W tile [32 k x 128 cols]
        #pragma unroll
        for (int i = 0; i < 4; i++) {
            int idx = i * 256 + tid;           // 0..1023
            int kk  = idx >> 5;
            int cq  = idx & 31;
            *(float4*)&ws[kk][cq * 4] = W4[(size_t)(kt + kk) * (HID / 4) + cq];
        }
        __syncthreads();

        #pragma unroll
        for (int kk = 0; kk < 32; kk++) {
            float4 b  = *(const float4*)&ws[kk][c0];
            float4 a0 = *(const float4*)&xs[kk][r0];
            float4 a1 = *(const float4*)&xs[kk][r0 + 4];
            float a[8] = {a0.x, a0.y, a0.z, a0.w, a1.x, a1.y, a1.z, a1.w};
            #pragma unroll
            for (int i = 0; i < 8; i++) {
                acc[i][0] += a[i] * b.x;
                acc[i][1] += a[i] * b.y;
                acc[i][2] += a[i] * b.z;
                acc[i][3] += a[i] * b.w;
            }
        }
        __syncthreads();
    }

    float4 bcv = *(const float4*)&bc[c0];
    #pragma unroll
    for (int i = 0; i < 8; i++) {
        int node = row0 + r0 + i;
        if (node < NN) {
            float di = g_dinv[node];
            float4 hv, av;
            hv.x = acc[i][0] * di; hv.y = acc[i][1] * di;
            hv.z = acc[i][2] * di; hv.w = acc[i][3] * di;
            av.x = bcv.x + hv.x * di; av.y = bcv.y + hv.y * di;
            av.z = bcv.z + hv.z * di; av.w = bcv.w + hv.w * di;
            *(float4*)&g_hs [(size_t)node * HID + c0] = hv;
            *(float4*)&g_agg[(size_t)node * HID + c0] = av;
        }
    }
}

// ---------------------------------------------------------------------------
// K4: edge scatter.  agg[dst] += hs[src] * dinv[dst]
// One warp = 32 edges per batch; lane holds one float4 (128/32*4) of the row.
// Vector reductions via red.global.add.v4.f32 (no return => REDG fast path).
// ---------------------------------------------------------------------------
__global__ __launch_bounds__(256) void k_scatter(const void* __restrict__ eptr) {
    const long long* e64 = (const long long*)eptr;
    const int*       e32 = (const int*)eptr;
    const int is64 = g_is64;
    const int lane = threadIdx.x & 31;
    const int warp = (blockIdx.x * blockDim.x + threadIdx.x) >> 5;
    const int nw   = (gridDim.x * blockDim.x) >> 5;
    const float4* hs4  = (const float4*)g_hs;
    float4*       agg4 = (float4*)g_agg;

    // NE % 32 == 0, and all bases are multiples of 32 => full batches always.
    for (int base = warp * 32; base < NE; base += nw * 32) {
        int e = base + lane;
        int   s  = is64 ? (int)e64[e]      : e32[e];
        int   d  = is64 ? (int)e64[NE + e] : e32[NE + e];
        float nd = g_dinv[d];
        #pragma unroll 1
        for (int j = 0; j < 32; j++) {
            int   ss = __shfl_sync(0xffffffffu, s, j);
            int   dd = __shfl_sync(0xffffffffu, d, j);
            float nn = __shfl_sync(0xffffffffu, nd, j);
            float4 v = hs4[(size_t)ss * 32 + lane];
            float4* p = &agg4[(size_t)dd * 32 + lane];
            asm volatile("red.global.add.v4.f32 [%0], {%1,%2,%3,%4};"
                         :: "l"(p), "f"(v.x * nn), "f"(v.y * nn),
                            "f"(v.z * nn), "f"(v.w * nn)
                         : "memory");
        }
    }
}

// ---------------------------------------------------------------------------
// K5: relu -> @W_lin + b_lin -> log_softmax.  One node per thread.
// ---------------------------------------------------------------------------
__global__ __launch_bounds__(128) void k_final(const float* __restrict__ Wl,
                                               const float* __restrict__ bl,
                                               float* __restrict__ out) {
    __shared__ float sW[HID * COUT];   // 8KB
    __shared__ float sB[COUT];
    for (int i = threadIdx.x; i < HID * COUT; i += 128) sW[i] = Wl[i];
    if (threadIdx.x < COUT) sB[threadIdx.x] = bl[threadIdx.x];
    __syncthreads();

    int node = blockIdx.x * 128 + threadIdx.x;
    if (node >= NN) return;

    float acc[COUT];
    #pragma unroll
    for (int c = 0; c < COUT; c++) acc[c] = sB[c];

    const float4* a4 = (const float4*)(g_agg + (size_t)node * HID);
    #pragma unroll 4
    for (int k4 = 0; k4 < HID / 4; k4++) {
        float4 v = a4[k4];
        float vv[4];
        vv[0] = fmaxf(v.x, 0.f); vv[1] = fmaxf(v.y, 0.f);
        vv[2] = fmaxf(v.z, 0.f); vv[3] = fmaxf(v.w, 0.f);
        #pragma unroll
        for (int j = 0; j < 4; j++) {
            const float4* w4 = (const float4*)&sW[(k4 * 4 + j) * COUT];
            #pragma unroll
            for (int c4 = 0; c4 < 4; c4++) {
                float4 w = w4[c4];
                acc[c4 * 4 + 0] += vv[j] * w.x;
                acc[c4 * 4 + 1] += vv[j] * w.y;
                acc[c4 * 4 + 2] += vv[j] * w.z;
                acc[c4 * 4 + 3] += vv[j] * w.w;
            }
        }
    }

    float m = acc[0];
    #pragma unroll
    for (int c = 1; c < COUT; c++) m = fmaxf(m, acc[c]);
    float s = 0.f;
    #pragma unroll
    for (int c = 0; c < COUT; c++) s += expf(acc[c] - m);
    float l = m + logf(s);

    float* o = out + (size_t)node * COUT;
    #pragma unroll
    for (int c4 = 0; c4 < 4; c4++) {
        float4 ov;
        ov.x = acc[c4 * 4 + 0] - l;
        ov.y = acc[c4 * 4 + 1] - l;
        ov.z = acc[c4 * 4 + 2] - l;
        ov.w = acc[c4 * 4 + 3] - l;
        *(float4*)&o[c4 * 4] = ov;
    }
}

// ---------------------------------------------------------------------------
extern "C" void kernel_launch(void* const* d_in, const int* in_sizes, int n_in,
                              void* d_out, int out_size) {
    const float* x      = (const float*)d_in[0];
    const void*  eidx   = d_in[1];
    const float* W_conv = (const float*)d_in[2];
    const float* b_conv = (const float*)d_in[3];
    const float* W_lin  = (const float*)d_in[4];
    const float* b_lin  = (const float*)d_in[5];
    float* out = (float*)d_out;

    k_init<<<(NN + 255) / 256, 256>>>((const int*)eidx);
    k_deg<<<1024, 256>>>(eidx);
    k_dinv<<<(NN + 255) / 256, 256>>>();
    k_gemm<<<(NN + 63) / 64, 256>>>(x, W_conv, b_conv);
    k_scatter<<<2048, 256>>>(eidx);
    k_final<<<(NN + 127) / 128, 128>>>(W_lin, b_lin, out);
}

// round 3
// speedup vs baseline: 1.0703x; 1.0703x over previous
#include <cuda_runtime.h>
#include <cuda_bf16.h>
#include <cuda_fp16.h>
#include <math.h>
#include <stdint.h>

#define NN   100000
#define NE   1600000
#define CIN  256
#define HID  128
#define COUT 16

// ---------------- scratch (__device__ globals; no allocs allowed) ----------
__device__ __half          g_hs16[(size_t)NN * HID];   // messages, fp16
__device__ float           g_agg[(size_t)NN * HID];    // aggregation accumulator
__device__ int             g_deg[NN];
__device__ float           g_dinv[NN];
__device__ int             g_is64;
__device__ __nv_bfloat16   g_WhiT[HID * CIN];          // W^T hi  [n][k]
__device__ __nv_bfloat16   g_WloT[HID * CIN];          // W^T lo  [n][k]

__device__ __forceinline__ uint32_t smem_u32(const void* p) {
    uint32_t a;
    asm("{ .reg .u64 t; cvta.to.shared.u64 t, %1; cvt.u32.u64 %0, t; }"
        : "=r"(a) : "l"(p));
    return a;
}
__device__ __forceinline__ uint32_t swz128(uint32_t off) {
    return off ^ ((off >> 3) & 0x70);
}
__device__ __forceinline__ void ldsm_x4(uint32_t* r, uint32_t addr) {
    asm volatile("ldmatrix.sync.aligned.m8n8.x4.shared.b16 {%0,%1,%2,%3}, [%4];"
                 : "=r"(r[0]), "=r"(r[1]), "=r"(r[2]), "=r"(r[3]) : "r"(addr));
}
__device__ __forceinline__ void mma_bf16(float* d, const uint32_t* a,
                                         uint32_t b0, uint32_t b1) {
    asm volatile("mma.sync.aligned.m16n8k16.row.col.f32.bf16.bf16.f32 "
                 "{%0,%1,%2,%3}, {%4,%5,%6,%7}, {%8,%9}, {%0,%1,%2,%3};"
                 : "+f"(d[0]), "+f"(d[1]), "+f"(d[2]), "+f"(d[3])
                 : "r"(a[0]), "r"(a[1]), "r"(a[2]), "r"(a[3]), "r"(b0), "r"(b1));
}

// ---------------------------------------------------------------------------
// K0: init degrees (self-loop => 1), sniff edge dtype (int64 vs int32)
// ---------------------------------------------------------------------------
__global__ void k_init(const int* __restrict__ e32) {
    int i = blockIdx.x * blockDim.x + threadIdx.x;
    if (i < NN) g_deg[i] = 1;
    if (i == 0) {
        int is64 = 1;
        #pragma unroll 1
        for (int j = 0; j < 64; j++)
            if (e32[2 * j + 1] != 0) { is64 = 0; break; }
        g_is64 = is64;
    }
}

__global__ void k_deg(const void* __restrict__ eptr) {
    const long long* e64 = (const long long*)eptr;
    const int*       e32 = (const int*)eptr;
    const int is64 = g_is64;
    for (int e = blockIdx.x * blockDim.x + threadIdx.x; e < NE;
         e += gridDim.x * blockDim.x) {
        int d = is64 ? (int)e64[NE + e] : e32[NE + e];
        atomicAdd(&g_deg[d], 1);
    }
}

__global__ void k_dinv() {
    int i = blockIdx.x * blockDim.x + threadIdx.x;
    if (i < NN) g_dinv[i] = rsqrtf((float)g_deg[i]);
}

// split W into bf16 hi/lo, transposed to [n][k]
__global__ void k_wsplit(const float* __restrict__ W) {
    int i = blockIdx.x * blockDim.x + threadIdx.x;
    if (i < CIN * HID) {
        int k = i >> 7, n = i & 127;
        float w = W[i];
        __nv_bfloat16 hi = __float2bfloat16_rn(w);
        float r = w - __bfloat162float(hi);
        g_WhiT[n * CIN + k] = hi;
        g_WloT[n * CIN + k] = __float2bfloat16_rn(r);
    }
}

// ---------------------------------------------------------------------------
// K3: h = x @ W_conv via bf16-split mma.sync (HMMA), fp32 register accum.
// CTA tile M=128 x N=128, K-chunks of 64 (4 chunks). 8 warps: wm=wid&3
// (32 rows), wn=wid>>2 (64 cols). Warp tile 32x64 = 2x8 m16n8 frags.
// Epilogue: hs16 = fp16(h*dinv); agg = b_conv + h*dinv^2.
// ---------------------------------------------------------------------------
#define TILE_B   16384    // 128 rows x 64 bf16 (128B rows)
#define OFF_AHI  0
#define OFF_ALO  16384
#define OFF_BHI  32768
#define OFF_BLO  49152
#define SMEM_DYN (4 * TILE_B + 256)

__global__ __launch_bounds__(256, 1) void k_gemm_tc(const float* __restrict__ x,
                                                    const float* __restrict__ bc) {
    extern __shared__ char dsm_raw[];
    char* const base = (char*)(((uintptr_t)dsm_raw + 127) & ~(uintptr_t)127);
    const uint32_t base_u = smem_u32(base);

    const int tid  = threadIdx.x;
    const int lane = tid & 31;
    const int wid  = tid >> 5;
    const int wm   = wid & 3;        // row quarter (32 rows)
    const int wn   = wid >> 2;       // col half (64 cols)
    const int row0 = blockIdx.x * 128;

    float acc[2][8][4];
    #pragma unroll
    for (int i = 0; i < 2; i++)
        #pragma unroll
        for (int j = 0; j < 8; j++)
            #pragma unroll
            for (int q = 0; q < 4; q++) acc[i][j][q] = 0.f;

    const float4* x4 = (const float4*)x;

    for (int c = 0; c < 4; c++) {
        // ---- convert x chunk [128 x 64] -> A_hi/A_lo bf16 (SW128) ----
        #pragma unroll
        for (int i = 0; i < 8; i++) {
            int idx = i * 256 + tid;          // 0..2047
            int r   = idx >> 4;               // row 0..127
            int q   = idx & 15;               // float4 index within 64-k chunk
            int node = row0 + r;
            float4 v = make_float4(0.f, 0.f, 0.f, 0.f);
            if (node < NN) v = x4[(size_t)node * (CIN / 4) + c * 16 + q];

            __nv_bfloat16 hx = __float2bfloat16_rn(v.x);
            __nv_bfloat16 hy = __float2bfloat16_rn(v.y);
            __nv_bfloat16 hz = __float2bfloat16_rn(v.z);
            __nv_bfloat16 hw = __float2bfloat16_rn(v.w);
            __nv_bfloat16 lx = __float2bfloat16_rn(v.x - __bfloat162float(hx));
            __nv_bfloat16 ly = __float2bfloat16_rn(v.y - __bfloat162float(hy));
            __nv_bfloat16 lz = __float2bfloat16_rn(v.z - __bfloat162float(hz));
            __nv_bfloat16 lw = __float2bfloat16_rn(v.w - __bfloat162float(hw));

            __nv_bfloat162 h01; h01.x = hx; h01.y = hy;
            __nv_bfloat162 h23; h23.x = hz; h23.y = hw;
            __nv_bfloat162 l01; l01.x = lx; l01.y = ly;
            __nv_bfloat162 l23; l23.x = lz; l23.y = lw;

            uint32_t so = swz128((uint32_t)(r * 128 + q * 8));
            *(uint2*)(base + OFF_AHI + so) =
                make_uint2(*(uint32_t*)&h01, *(uint32_t*)&h23);
            *(uint2*)(base + OFF_ALO + so) =
                make_uint2(*(uint32_t*)&l01, *(uint32_t*)&l23);
        }
        // ---- copy W^T chunk [128 n x 64 k] -> B_hi/B_lo ----
        #pragma unroll
        for (int i = 0; i < 4; i++) {
            int idx = i * 256 + tid;          // 0..1023
            int n   = idx >> 3;               // row 0..127
            int u   = idx & 7;                // 16B unit
            uint32_t so = swz128((uint32_t)(n * 128 + u * 16));
            const char* srcH = (const char*)g_WhiT + n * (CIN * 2) + c * 128 + u * 16;
            const char* srcL = (const char*)g_WloT + n * (CIN * 2) + c * 128 + u * 16;
            *(uint4*)(base + OFF_BHI + so) = *(const uint4*)srcH;
            *(uint4*)(base + OFF_BLO + so) = *(const uint4*)srcL;
        }
        __syncthreads();

        // ---- mma over 4 k-steps of 16, 3 split terms ----
        #pragma unroll
        for (int ks = 0; ks < 4; ks++) {
            // A fragments: rows wm*32 + mi*16 + (lane%16), kbyte ks*32 + (lane/16)*16
            uint32_t ah[2][4], al[2][4];
            #pragma unroll
            for (int mi = 0; mi < 2; mi++) {
                uint32_t r = (uint32_t)(wm * 32 + mi * 16 + (lane & 15));
                uint32_t kb = (uint32_t)(ks * 32 + (lane >> 4) * 16);
                uint32_t so = swz128(r * 128 + kb);
                ldsm_x4(ah[mi], base_u + OFF_AHI + so);
                ldsm_x4(al[mi], base_u + OFF_ALO + so);
            }
            #pragma unroll
            for (int nj2 = 0; nj2 < 4; nj2++) {
                // B x4: two n8 tiles. lanes: 0-7 n0-7/k0, 8-15 n0-7/k8,
                // 16-23 n8-15/k0, 24-31 n8-15/k8
                uint32_t n = (uint32_t)(wn * 64 + nj2 * 16 + (lane & 7)
                                        + ((lane >> 4) << 3));
                uint32_t kb = (uint32_t)(ks * 32 + ((lane >> 3) & 1) * 16);
                uint32_t so = swz128(n * 128 + kb);
                uint32_t bh[4], bl[4];
                ldsm_x4(bh, base_u + OFF_BHI + so);
                ldsm_x4(bl, base_u + OFF_BLO + so);
                #pragma unroll
                for (int mi = 0; mi < 2; mi++) {
                    mma_bf16(acc[mi][nj2 * 2 + 0], ah[mi], bh[0], bh[1]);
                    mma_bf16(acc[mi][nj2 * 2 + 1], ah[mi], bh[2], bh[3]);
                    mma_bf16(acc[mi][nj2 * 2 + 0], ah[mi], bl[0], bl[1]);
                    mma_bf16(acc[mi][nj2 * 2 + 1], ah[mi], bl[2], bl[3]);
                    mma_bf16(acc[mi][nj2 * 2 + 0], al[mi], bh[0], bh[1]);
                    mma_bf16(acc[mi][nj2 * 2 + 1], al[mi], bh[2], bh[3]);
                }
            }
        }
        __syncthreads();
    }

    // ---- epilogue ----
    const int group = lane >> 2;      // 0..7
    const int qp    = lane & 3;       // 0..3 -> col pair
    #pragma unroll
    for (int mi = 0; mi < 2; mi++) {
        #pragma unroll
        for (int half = 0; half < 2; half++) {      // c0c1 (row) / c2c3 (row+8)
            int r = wm * 32 + mi * 16 + half * 8 + group;
            int node = row0 + r;
            if (node < NN) {
                float di = g_dinv[node];
                __half* hrow = g_hs16 + (size_t)node * HID;
                float*  arow = g_agg  + (size_t)node * HID;
                #pragma unroll
                for (int nj = 0; nj < 8; nj++) {
                    int col = wn * 64 + nj * 8 + qp * 2;
                    float c0 = acc[mi][nj][half * 2 + 0];
                    float c1 = acc[mi][nj][half * 2 + 1];
                    float h0 = c0 * di, h1 = c1 * di;
                    __half2 hh = __floats2half2_rn(h0, h1);
                    *(__half2*)(hrow + col) = hh;
                    float2 av;
                    av.x = __ldg(bc + col)     + h0 * di;
                    av.y = __ldg(bc + col + 1) + h1 * di;
                    *(float2*)(arow + col) = av;
                }
            }
        }
    }
}

// ---------------------------------------------------------------------------
// K4: edge scatter.  agg[dst] += fp32(hs16[src]) * dinv[dst]
// ---------------------------------------------------------------------------
__global__ __launch_bounds__(256) void k_scatter(const void* __restrict__ eptr) {
    const long long* e64 = (const long long*)eptr;
    const int*       e32 = (const int*)eptr;
    const int is64 = g_is64;
    const int lane = threadIdx.x & 31;
    const int warp = (blockIdx.x * blockDim.x + threadIdx.x) >> 5;
    const int nw   = (gridDim.x * blockDim.x) >> 5;
    const uint2* hs2 = (const uint2*)g_hs16;
    float4*      agg4 = (float4*)g_agg;

    for (int base = warp * 32; base < NE; base += nw * 32) {
        int e = base + lane;
        int   s  = is64 ? (int)e64[e]      : e32[e];
        int   d  = is64 ? (int)e64[NE + e] : e32[NE + e];
        float nd = g_dinv[d];
        #pragma unroll 1
        for (int j = 0; j < 32; j++) {
            int   ss = __shfl_sync(0xffffffffu, s, j);
            int   dd = __shfl_sync(0xffffffffu, d, j);
            float nn = __shfl_sync(0xffffffffu, nd, j);
            uint2 v = hs2[(size_t)ss * 32 + lane];
            float2 f0 = __half22float2(*(__half2*)&v.x);
            float2 f1 = __half22float2(*(__half2*)&v.y);
            float4* p = &agg4[(size_t)dd * 32 + lane];
            asm volatile("red.global.add.v4.f32 [%0], {%1,%2,%3,%4};"
                         :: "l"(p), "f"(f0.x * nn), "f"(f0.y * nn),
                            "f"(f1.x * nn), "f"(f1.y * nn)
                         : "memory");
        }
    }
}

// ---------------------------------------------------------------------------
// K5: relu -> @W_lin + b_lin -> log_softmax
// ---------------------------------------------------------------------------
__global__ __launch_bounds__(128) void k_final(const float* __restrict__ Wl,
                                               const float* __restrict__ bl,
                                               float* __restrict__ out) {
    __shared__ float sW[HID * COUT];
    __shared__ float sB[COUT];
    for (int i = threadIdx.x; i < HID * COUT; i += 128) sW[i] = Wl[i];
    if (threadIdx.x < COUT) sB[threadIdx.x] = bl[threadIdx.x];
    __syncthreads();

    int node = blockIdx.x * 128 + threadIdx.x;
    if (node >= NN) return;

    float acc[COUT];
    #pragma unroll
    for (int c = 0; c < COUT; c++) acc[c] = sB[c];

    const float4* a4 = (const float4*)(g_agg + (size_t)node * HID);
    #pragma unroll 4
    for (int k4 = 0; k4 < HID / 4; k4++) {
        float4 v = a4[k4];
        float vv[4];
        vv[0] = fmaxf(v.x, 0.f); vv[1] = fmaxf(v.y, 0.f);
        vv[2] = fmaxf(v.z, 0.f); vv[3] = fmaxf(v.w, 0.f);
        #pragma unroll
        for (int j = 0; j < 4; j++) {
            const float4* w4 = (const float4*)&sW[(k4 * 4 + j) * COUT];
            #pragma unroll
            for (int c4 = 0; c4 < 4; c4++) {
                float4 wv = w4[c4];
                acc[c4 * 4 + 0] += vv[j] * wv.x;
                acc[c4 * 4 + 1] += vv[j] * wv.y;
                acc[c4 * 4 + 2] += vv[j] * wv.z;
                acc[c4 * 4 + 3] += vv[j] * wv.w;
            }
        }
    }

    float m = acc[0];
    #pragma unroll
    for (int c = 1; c < COUT; c++) m = fmaxf(m, acc[c]);
    float s = 0.f;
    #pragma unroll
    for (int c = 0; c < COUT; c++) s += expf(acc[c] - m);
    float l = m + logf(s);

    float* o = out + (size_t)node * COUT;
    #pragma unroll
    for (int c4 = 0; c4 < 4; c4++) {
        float4 ov;
        ov.x = acc[c4 * 4 + 0] - l;
        ov.y = acc[c4 * 4 + 1] - l;
        ov.z = acc[c4 * 4 + 2] - l;
        ov.w = acc[c4 * 4 + 3] - l;
        *(float4*)&o[c4 * 4] = ov;
    }
}

// ---------------------------------------------------------------------------
extern "C" void kernel_launch(void* const* d_in, const int* in_sizes, int n_in,
                              void* d_out, int out_size) {
    const float* x      = (const float*)d_in[0];
    const void*  eidx   = d_in[1];
    const float* W_conv = (const float*)d_in[2];
    const float* b_conv = (const float*)d_in[3];
    const float* W_lin  = (const float*)d_in[4];
    const float* b_lin  = (const float*)d_in[5];
    float* out = (float*)d_out;

    cudaFuncSetAttribute(k_gemm_tc, cudaFuncAttributeMaxDynamicSharedMemorySize,
                         SMEM_DYN);

    k_init<<<(NN + 255) / 256, 256>>>((const int*)eidx);
    k_deg<<<1024, 256>>>(eidx);
    k_dinv<<<(NN + 255) / 256, 256>>>();
    k_wsplit<<<(CIN * HID + 255) / 256, 256>>>(W_conv);
    k_gemm_tc<<<(NN + 127) / 128, 256, SMEM_DYN>>>(x, b_conv);
    k_scatter<<<2048, 256>>>(eidx);
    k_final<<<(NN + 127) / 128, 128>>>(W_lin, b_lin, out);
}

// round 4
// speedup vs baseline: 1.3086x; 1.2227x over previous
#include <cuda_runtime.h>
#include <cuda_bf16.h>
#include <cuda_fp16.h>
#include <math.h>
#include <stdint.h>

#define NN   100000
#define NE   1600000
#define CIN  256
#define HID  128
#define COUT 16
#define NBLK 98          // ceil(NN/1024)

// ---------------- scratch (__device__ globals; no allocs allowed) ----------
__device__ __half          g_hs16[(size_t)NN * HID];   // messages h*dinv[src], fp16
__device__ int             g_deg[NN];                  // edge-only in-degree
__device__ float           g_dinv[NN];                 // rsqrt(deg+1)
__device__ int             g_psc[NN];                  // per-block exclusive scan
__device__ int             g_off[NN + 1];              // CSR offsets (by dst)
__device__ int             g_wptr[NN];                 // write cursors
__device__ int             g_bsum[NBLK];
__device__ int             g_boff[NBLK];
__device__ int             g_esrc[NE];                 // dst-sorted src indices
__device__ int             g_is64;
__device__ __nv_bfloat16   g_WhiT[HID * CIN];          // W^T hi  [n][k]
__device__ __nv_bfloat16   g_WloT[HID * CIN];          // W^T lo  [n][k]

__device__ __forceinline__ uint32_t smem_u32(const void* p) {
    uint32_t a;
    asm("{ .reg .u64 t; cvta.to.shared.u64 t, %1; cvt.u32.u64 %0, t; }"
        : "=r"(a) : "l"(p));
    return a;
}
__device__ __forceinline__ uint32_t swz128(uint32_t off) {
    return off ^ ((off >> 3) & 0x70);
}
__device__ __forceinline__ void ldsm_x4(uint32_t* r, uint32_t addr) {
    asm volatile("ldmatrix.sync.aligned.m8n8.x4.shared.b16 {%0,%1,%2,%3}, [%4];"
                 : "=r"(r[0]), "=r"(r[1]), "=r"(r[2]), "=r"(r[3]) : "r"(addr));
}
__device__ __forceinline__ void mma_bf16(float* d, const uint32_t* a,
                                         uint32_t b0, uint32_t b1) {
    asm volatile("mma.sync.aligned.m16n8k16.row.col.f32.bf16.bf16.f32 "
                 "{%0,%1,%2,%3}, {%4,%5,%6,%7}, {%8,%9}, {%0,%1,%2,%3};"
                 : "+f"(d[0]), "+f"(d[1]), "+f"(d[2]), "+f"(d[3])
                 : "r"(a[0]), "r"(a[1]), "r"(a[2]), "r"(a[3]), "r"(b0), "r"(b1));
}

// ---------------------------------------------------------------------------
// K0: zero degrees, sniff edge dtype (int64 vs int32)
// ---------------------------------------------------------------------------
__global__ void k_init(const int* __restrict__ e32) {
    int i = blockIdx.x * blockDim.x + threadIdx.x;
    if (i < NN) g_deg[i] = 0;
    if (i == 0) {
        int is64 = 1;
        #pragma unroll 1
        for (int j = 0; j < 64; j++)
            if (e32[2 * j + 1] != 0) { is64 = 0; break; }
        g_is64 = is64;
    }
}

__global__ void k_deg(const void* __restrict__ eptr) {
    const long long* e64 = (const long long*)eptr;
    const int*       e32 = (const int*)eptr;
    const int is64 = g_is64;
    for (int e = blockIdx.x * blockDim.x + threadIdx.x; e < NE;
         e += gridDim.x * blockDim.x) {
        int d = is64 ? (int)e64[NE + e] : e32[NE + e];
        atomicAdd(&g_deg[d], 1);
    }
}

// ---- exclusive scan of g_deg (3 kernels) ----------------------------------
__global__ __launch_bounds__(1024) void k_scanA() {
    __shared__ int ss[1024];
    const int t = threadIdx.x;
    const int i = blockIdx.x * 1024 + t;
    int v = (i < NN) ? g_deg[i] : 0;
    ss[t] = v;
    __syncthreads();
    #pragma unroll
    for (int off = 1; off < 1024; off <<= 1) {
        int add = (t >= off) ? ss[t - off] : 0;
        __syncthreads();
        ss[t] += add;
        __syncthreads();
    }
    if (i < NN) g_psc[i] = ss[t] - v;
    if (t == 1023) g_bsum[blockIdx.x] = ss[1023];
}

__global__ void k_scanB() {
    if (threadIdx.x == 0) {
        int run = 0;
        #pragma unroll 1
        for (int b = 0; b < NBLK; b++) { g_boff[b] = run; run += g_bsum[b]; }
        g_off[NN] = run;   // == NE
    }
}

__global__ void k_scanC() {
    int i = blockIdx.x * blockDim.x + threadIdx.x;
    if (i < NN) {
        int o = g_psc[i] + g_boff[i >> 10];
        g_off[i]  = o;
        g_wptr[i] = o;
        g_dinv[i] = rsqrtf((float)(g_deg[i] + 1));   // +1 self-loop
    }
}

// ---- scatter edges into dst-sorted order ----------------------------------
__global__ void k_sort(const void* __restrict__ eptr) {
    const long long* e64 = (const long long*)eptr;
    const int*       e32 = (const int*)eptr;
    const int is64 = g_is64;
    for (int e = blockIdx.x * blockDim.x + threadIdx.x; e < NE;
         e += gridDim.x * blockDim.x) {
        int s = is64 ? (int)e64[e]      : e32[e];
        int d = is64 ? (int)e64[NE + e] : e32[NE + e];
        int pos = atomicAdd(&g_wptr[d], 1);
        g_esrc[pos] = s;
    }
}

// ---- split W into bf16 hi/lo, transposed to [n][k] ------------------------
__global__ void k_wsplit(const float* __restrict__ W) {
    int i = blockIdx.x * blockDim.x + threadIdx.x;
    if (i < CIN * HID) {
        int k = i >> 7, n = i & 127;
        float w = W[i];
        __nv_bfloat16 hi = __float2bfloat16_rn(w);
        float r = w - __bfloat162float(hi);
        g_WhiT[n * CIN + k] = hi;
        g_WloT[n * CIN + k] = __float2bfloat16_rn(r);
    }
}

// ---------------------------------------------------------------------------
// GEMM: h = x @ W_conv via bf16-split mma.sync, fp32 accum.
// CTA tile 128x128, K in 4 chunks of 64. Epilogue writes only hs16 = h*dinv.
// ---------------------------------------------------------------------------
#define TILE_B   16384
#define OFF_AHI  0
#define OFF_ALO  16384
#define OFF_BHI  32768
#define OFF_BLO  49152
#define SMEM_DYN (4 * TILE_B + 256)

__global__ __launch_bounds__(256, 2) void k_gemm_tc(const float* __restrict__ x) {
    extern __shared__ char dsm_raw[];
    char* const base = (char*)(((uintptr_t)dsm_raw + 127) & ~(uintptr_t)127);
    const uint32_t base_u = smem_u32(base);

    const int tid  = threadIdx.x;
    const int lane = tid & 31;
    const int wid  = tid >> 5;
    const int wm   = wid & 3;
    const int wn   = wid >> 2;
    const int row0 = blockIdx.x * 128;

    float acc[2][8][4];
    #pragma unroll
    for (int i = 0; i < 2; i++)
        #pragma unroll
        for (int j = 0; j < 8; j++)
            #pragma unroll
            for (int q = 0; q < 4; q++) acc[i][j][q] = 0.f;

    const float4* x4 = (const float4*)x;

    float4 v[8];
    // preload chunk 0
    #pragma unroll
    for (int i = 0; i < 8; i++) {
        int idx = i * 256 + tid;
        int r = idx >> 4, q = idx & 15;
        int node = row0 + r;
        v[i] = (node < NN) ? x4[(size_t)node * (CIN / 4) + q]
                           : make_float4(0.f, 0.f, 0.f, 0.f);
    }

    for (int c = 0; c < 4; c++) {
        // ---- convert prefetched x chunk -> A_hi/A_lo (bf16, SW128) ----
        #pragma unroll
        for (int i = 0; i < 8; i++) {
            int idx = i * 256 + tid;
            int r = idx >> 4, q = idx & 15;
            float4 w = v[i];
            __nv_bfloat16 hx = __float2bfloat16_rn(w.x);
            __nv_bfloat16 hy = __float2bfloat16_rn(w.y);
            __nv_bfloat16 hz = __float2bfloat16_rn(w.z);
            __nv_bfloat16 hw = __float2bfloat16_rn(w.w);
            __nv_bfloat16 lx = __float2bfloat16_rn(w.x - __bfloat162float(hx));
            __nv_bfloat16 ly = __float2bfloat16_rn(w.y - __bfloat162float(hy));
            __nv_bfloat16 lz = __float2bfloat16_rn(w.z - __bfloat162float(hz));
            __nv_bfloat16 lw = __float2bfloat16_rn(w.w - __bfloat162float(hw));
            __nv_bfloat162 h01; h01.x = hx; h01.y = hy;
            __nv_bfloat162 h23; h23.x = hz; h23.y = hw;
            __nv_bfloat162 l01; l01.x = lx; l01.y = ly;
            __nv_bfloat162 l23; l23.x = lz; l23.y = lw;
            uint32_t so = swz128((uint32_t)(r * 128 + q * 8));
            *(uint2*)(base + OFF_AHI + so) =
                make_uint2(*(uint32_t*)&h01, *(uint32_t*)&h23);
            *(uint2*)(base + OFF_ALO + so) =
                make_uint2(*(uint32_t*)&l01, *(uint32_t*)&l23);
        }
        // ---- W^T chunk -> B_hi/B_lo ----
        #pragma unroll
        for (int i = 0; i < 4; i++) {
            int idx = i * 256 + tid;
            int n = idx >> 3, u = idx & 7;
            uint32_t so = swz128((uint32_t)(n * 128 + u * 16));
            const char* srcH = (const char*)g_WhiT + n * (CIN * 2) + c * 128 + u * 16;
            const char* srcL = (const char*)g_WloT + n * (CIN * 2) + c * 128 + u * 16;
            *(uint4*)(base + OFF_BHI + so) = *(const uint4*)srcH;
            *(uint4*)(base + OFF_BLO + so) = *(const uint4*)srcL;
        }
        __syncthreads();

        // prefetch next chunk while MMAs run
        if (c < 3) {
            #pragma unroll
            for (int i = 0; i < 8; i++) {
                int idx = i * 256 + tid;
                int r = idx >> 4, q = idx & 15;
                int node = row0 + r;
                v[i] = (node < NN)
                     ? x4[(size_t)node * (CIN / 4) + (c + 1) * 16 + q]
                     : make_float4(0.f, 0.f, 0.f, 0.f);
            }
        }

        #pragma unroll
        for (int ks = 0; ks < 4; ks++) {
            uint32_t ah[2][4], al[2][4];
            #pragma unroll
            for (int mi = 0; mi < 2; mi++) {
                uint32_t r = (uint32_t)(wm * 32 + mi * 16 + (lane & 15));
                uint32_t kb = (uint32_t)(ks * 32 + (lane >> 4) * 16);
                uint32_t so = swz128(r * 128 + kb);
                ldsm_x4(ah[mi], base_u + OFF_AHI + so);
                ldsm_x4(al[mi], base_u + OFF_ALO + so);
            }
            #pragma unroll
            for (int nj2 = 0; nj2 < 4; nj2++) {
                uint32_t n = (uint32_t)(wn * 64 + nj2 * 16 + (lane & 7)
                                        + ((lane >> 4) << 3));
                uint32_t kb = (uint32_t)(ks * 32 + ((lane >> 3) & 1) * 16);
                uint32_t so = swz128(n * 128 + kb);
                uint32_t bh[4], bl[4];
                ldsm_x4(bh, base_u + OFF_BHI + so);
                ldsm_x4(bl, base_u + OFF_BLO + so);
                #pragma unroll
                for (int mi = 0; mi < 2; mi++) {
                    mma_bf16(acc[mi][nj2 * 2 + 0], ah[mi], bh[0], bh[1]);
                    mma_bf16(acc[mi][nj2 * 2 + 1], ah[mi], bh[2], bh[3]);
                    mma_bf16(acc[mi][nj2 * 2 + 0], ah[mi], bl[0], bl[1]);
                    mma_bf16(acc[mi][nj2 * 2 + 1], ah[mi], bl[2], bl[3]);
                    mma_bf16(acc[mi][nj2 * 2 + 0], al[mi], bh[0], bh[1]);
                    mma_bf16(acc[mi][nj2 * 2 + 1], al[mi], bh[2], bh[3]);
                }
            }
        }
        __syncthreads();
    }

    // ---- epilogue: hs16 = h * dinv[node] ----
    const int group = lane >> 2;
    const int qp    = lane & 3;
    #pragma unroll
    for (int mi = 0; mi < 2; mi++) {
        #pragma unroll
        for (int half = 0; half < 2; half++) {
            int r = wm * 32 + mi * 16 + half * 8 + group;
            int node = row0 + r;
            if (node < NN) {
                float di = g_dinv[node];
                __half* hrow = g_hs16 + (size_t)node * HID;
                #pragma unroll
                for (int nj = 0; nj < 8; nj++) {
                    int col = wn * 64 + nj * 8 + qp * 2;
                    __half2 hh = __floats2half2_rn(
                        acc[mi][nj][half * 2 + 0] * di,
                        acc[mi][nj][half * 2 + 1] * di);
                    *(__half2*)(hrow + col) = hh;
                }
            }
        }
    }
}

// ---------------------------------------------------------------------------
// Aggregate + final linear + log_softmax.  One warp per dst node.
// agg = b_conv + dinv[dst] * (hs16[dst] + sum_{src in edges(dst)} hs16[src])
// lane owns dims {l, l+32, l+64, l+96} (strided, conflict-free W reads)
// ---------------------------------------------------------------------------
__global__ __launch_bounds__(256) void k_agg_final(const float* __restrict__ bc,
                                                   const float* __restrict__ Wl,
                                                   const float* __restrict__ bl,
                                                   float* __restrict__ out) {
    __shared__ float sW[HID][COUT + 1];   // [dim][class], pad -> conflict-free
    __shared__ float sBc[HID];
    __shared__ float sBl[COUT];
    for (int i = threadIdx.x; i < HID * COUT; i += 256) {
        int d = i >> 4, c = i & 15;
        sW[d][c] = Wl[i];
    }
    for (int i = threadIdx.x; i < HID; i += 256) sBc[i] = bc[i];
    if (threadIdx.x < COUT) sBl[threadIdx.x] = bl[threadIdx.x];
    __syncthreads();

    const int lane = threadIdx.x & 31;
    const int dst  = (blockIdx.x * blockDim.x + threadIdx.x) >> 5;
    if (dst >= NN) return;

    const int s0 = g_off[dst];
    const int s1 = g_off[dst + 1];
    const float di = g_dinv[dst];
    const __half* hs = g_hs16;

    float acc0, acc1, acc2, acc3;
    {   // self row
        const __half* r = hs + (size_t)dst * HID + lane;
        acc0 = __half2float(r[0]);
        acc1 = __half2float(r[32]);
        acc2 = __half2float(r[64]);
        acc3 = __half2float(r[96]);
    }
    for (int b = s0; b < s1; b += 32) {
        int m = s1 - b; if (m > 32) m = 32;
        int s = (lane < m) ? g_esrc[b + lane] : 0;
        #pragma unroll 1
        for (int j = 0; j < m; j++) {
            int ss = __shfl_sync(0xffffffffu, s, j);
            const __half* r = hs + (size_t)ss * HID + lane;
            acc0 += __half2float(r[0]);
            acc1 += __half2float(r[32]);
            acc2 += __half2float(r[64]);
            acc3 += __half2float(r[96]);
        }
    }

    acc0 = fmaxf(acc0 * di + sBc[lane],      0.f);
    acc1 = fmaxf(acc1 * di + sBc[lane + 32], 0.f);
    acc2 = fmaxf(acc2 * di + sBc[lane + 64], 0.f);
    acc3 = fmaxf(acc3 * di + sBc[lane + 96], 0.f);

    float p[COUT];
    #pragma unroll
    for (int c = 0; c < COUT; c++) {
        p[c] = acc0 * sW[lane][c] + acc1 * sW[lane + 32][c]
             + acc2 * sW[lane + 64][c] + acc3 * sW[lane + 96][c];
    }
    // butterfly reduce across warp
    #pragma unroll
    for (int off = 16; off > 0; off >>= 1)
        #pragma unroll
        for (int c = 0; c < COUT; c++)
            p[c] += __shfl_xor_sync(0xffffffffu, p[c], off);

    #pragma unroll
    for (int c = 0; c < COUT; c++) p[c] += sBl[c];

    float mx = p[0];
    #pragma unroll
    for (int c = 1; c < COUT; c++) mx = fmaxf(mx, p[c]);
    float sum = 0.f;
    #pragma unroll
    for (int c = 0; c < COUT; c++) sum += expf(p[c] - mx);
    float lse = mx + logf(sum);

    if (lane < COUT) out[(size_t)dst * COUT + lane] = p[lane] - lse;
}

// ---------------------------------------------------------------------------
extern "C" void kernel_launch(void* const* d_in, const int* in_sizes, int n_in,
                              void* d_out, int out_size) {
    const float* x      = (const float*)d_in[0];
    const void*  eidx   = d_in[1];
    const float* W_conv = (const float*)d_in[2];
    const float* b_conv = (const float*)d_in[3];
    const float* W_lin  = (const float*)d_in[4];
    const float* b_lin  = (const float*)d_in[5];
    float* out = (float*)d_out;

    cudaFuncSetAttribute(k_gemm_tc, cudaFuncAttributeMaxDynamicSharedMemorySize,
                         SMEM_DYN);

    k_init<<<(NN + 255) / 256, 256>>>((const int*)eidx);
    k_deg<<<1024, 256>>>(eidx);
    k_scanA<<<NBLK, 1024>>>();
    k_scanB<<<1, 32>>>();
    k_scanC<<<(NN + 255) / 256, 256>>>();
    k_sort<<<1024, 256>>>(eidx);
    k_wsplit<<<(CIN * HID + 255) / 256, 256>>>(W_conv);
    k_gemm_tc<<<(NN + 127) / 128, 256, SMEM_DYN>>>(x);
    k_agg_final<<<(NN * 32 + 255) / 256, 256>>>(b_conv, W_lin, b_lin, out);
}

// round 5
// speedup vs baseline: 1.3569x; 1.0370x over previous
#include <cuda_runtime.h>
#include <cuda_bf16.h>
#include <cuda_fp16.h>
#include <math.h>
#include <stdint.h>

#define NN   100000
#define NE   1600000
#define CIN  256
#define HID  128
#define COUT 16
#define NBLK 98          // ceil(NN/1024)

// ---------------- scratch (__device__ globals; no allocs allowed) ----------
__device__ __half          g_hs16[(size_t)NN * HID];   // messages h*dinv[src], fp16
__device__ int             g_deg[NN];                  // edge-only in-degree
__device__ float           g_dinv[NN];                 // rsqrt(deg+1)
__device__ int             g_psc[NN];                  // per-block exclusive scan
__device__ int             g_off[NN + 1];              // CSR offsets (by dst)
__device__ int             g_wptr[NN];                 // write cursors
__device__ int             g_bsum[NBLK];
__device__ int             g_boff[NBLK];
__device__ int             g_esrc[NE];                 // dst-sorted src indices
__device__ int             g_is64;
__device__ __nv_bfloat16   g_WhiT[HID * CIN];          // W^T hi  [n][k]
__device__ __nv_bfloat16   g_WloT[HID * CIN];          // W^T lo  [n][k]

__device__ __forceinline__ uint32_t smem_u32(const void* p) {
    uint32_t a;
    asm("{ .reg .u64 t; cvta.to.shared.u64 t, %1; cvt.u32.u64 %0, t; }"
        : "=r"(a) : "l"(p));
    return a;
}
__device__ __forceinline__ uint32_t swz128(uint32_t off) {
    return off ^ ((off >> 3) & 0x70);
}
__device__ __forceinline__ void ldsm_x4(uint32_t* r, uint32_t addr) {
    asm volatile("ldmatrix.sync.aligned.m8n8.x4.shared.b16 {%0,%1,%2,%3}, [%4];"
                 : "=r"(r[0]), "=r"(r[1]), "=r"(r[2]), "=r"(r[3]) : "r"(addr));
}
__device__ __forceinline__ void mma_bf16(float* d, const uint32_t* a,
                                         uint32_t b0, uint32_t b1) {
    asm volatile("mma.sync.aligned.m16n8k16.row.col.f32.bf16.bf16.f32 "
                 "{%0,%1,%2,%3}, {%4,%5,%6,%7}, {%8,%9}, {%0,%1,%2,%3};"
                 : "+f"(d[0]), "+f"(d[1]), "+f"(d[2]), "+f"(d[3])
                 : "r"(a[0]), "r"(a[1]), "r"(a[2]), "r"(a[3]), "r"(b0), "r"(b1));
}

// ---------------------------------------------------------------------------
__global__ void k_init(const int* __restrict__ e32) {
    int i = blockIdx.x * blockDim.x + threadIdx.x;
    if (i < NN) g_deg[i] = 0;
    if (i == 0) {
        int is64 = 1;
        #pragma unroll 1
        for (int j = 0; j < 64; j++)
            if (e32[2 * j + 1] != 0) { is64 = 0; break; }
        g_is64 = is64;
    }
}

__global__ void k_deg(const void* __restrict__ eptr) {
    const long long* e64 = (const long long*)eptr;
    const int*       e32 = (const int*)eptr;
    const int is64 = g_is64;
    for (int e = blockIdx.x * blockDim.x + threadIdx.x; e < NE;
         e += gridDim.x * blockDim.x) {
        int d = is64 ? (int)e64[NE + e] : e32[NE + e];
        atomicAdd(&g_deg[d], 1);
    }
}

// ---- exclusive scan of g_deg ----------------------------------------------
__global__ __launch_bounds__(1024) void k_scanA() {
    __shared__ int ss[1024];
    const int t = threadIdx.x;
    const int i = blockIdx.x * 1024 + t;
    int v = (i < NN) ? g_deg[i] : 0;
    ss[t] = v;
    __syncthreads();
    #pragma unroll
    for (int off = 1; off < 1024; off <<= 1) {
        int add = (t >= off) ? ss[t - off] : 0;
        __syncthreads();
        ss[t] += add;
        __syncthreads();
    }
    if (i < NN) g_psc[i] = ss[t] - v;
    if (t == 1023) g_bsum[blockIdx.x] = ss[1023];
}

// warp-parallel scan over NBLK block sums (NBLK <= 128)
__global__ __launch_bounds__(128) void k_scanB() {
    __shared__ int warp_tot[4];
    const int t = threadIdx.x;
    const int lane = t & 31, w = t >> 5;
    int v = (t < NBLK) ? g_bsum[t] : 0;
    int inc = v;
    #pragma unroll
    for (int off = 1; off < 32; off <<= 1) {
        int up = __shfl_up_sync(0xffffffffu, inc, off);
        if (lane >= off) inc += up;
    }
    if (lane == 31) warp_tot[w] = inc;
    __syncthreads();
    int pre = 0;
    #pragma unroll
    for (int j = 0; j < 4; j++) pre += (j < w) ? warp_tot[j] : 0;
    if (t < NBLK) g_boff[t] = pre + inc - v;
    if (t == 127) g_off[NN] = pre + inc;   // total == NE
}

__global__ void k_scanC() {
    int i = blockIdx.x * blockDim.x + threadIdx.x;
    if (i < NN) {
        int o = g_psc[i] + g_boff[i >> 10];
        g_off[i]  = o;
        g_wptr[i] = o;
        g_dinv[i] = rsqrtf((float)(g_deg[i] + 1));   // +1 self-loop
    }
}

__global__ void k_sort(const void* __restrict__ eptr) {
    const long long* e64 = (const long long*)eptr;
    const int*       e32 = (const int*)eptr;
    const int is64 = g_is64;
    for (int e = blockIdx.x * blockDim.x + threadIdx.x; e < NE;
         e += gridDim.x * blockDim.x) {
        int s = is64 ? (int)e64[e]      : e32[e];
        int d = is64 ? (int)e64[NE + e] : e32[NE + e];
        int pos = atomicAdd(&g_wptr[d], 1);
        g_esrc[pos] = s;
    }
}

__global__ void k_wsplit(const float* __restrict__ W) {
    int i = blockIdx.x * blockDim.x + threadIdx.x;
    if (i < CIN * HID) {
        int k = i >> 7, n = i & 127;
        float w = W[i];
        __nv_bfloat16 hi = __float2bfloat16_rn(w);
        float r = w - __bfloat162float(hi);
        g_WhiT[n * CIN + k] = hi;
        g_WloT[n * CIN + k] = __float2bfloat16_rn(r);
    }
}

// ---------------------------------------------------------------------------
// GEMM: h = x @ W_conv via bf16-split mma.sync, fp32 accum.
// ---------------------------------------------------------------------------
#define TILE_B   16384
#define OFF_AHI  0
#define OFF_ALO  16384
#define OFF_BHI  32768
#define OFF_BLO  49152
#define SMEM_DYN (4 * TILE_B + 256)

__global__ __launch_bounds__(256, 2) void k_gemm_tc(const float* __restrict__ x) {
    extern __shared__ char dsm_raw[];
    char* const base = (char*)(((uintptr_t)dsm_raw + 127) & ~(uintptr_t)127);
    const uint32_t base_u = smem_u32(base);

    const int tid  = threadIdx.x;
    const int lane = tid & 31;
    const int wid  = tid >> 5;
    const int wm   = wid & 3;
    const int wn   = wid >> 2;
    const int row0 = blockIdx.x * 128;

    float acc[2][8][4];
    #pragma unroll
    for (int i = 0; i < 2; i++)
        #pragma unroll
        for (int j = 0; j < 8; j++)
            #pragma unroll
            for (int q = 0; q < 4; q++) acc[i][j][q] = 0.f;

    const float4* x4 = (const float4*)x;

    float4 v[8];
    #pragma unroll
    for (int i = 0; i < 8; i++) {
        int idx = i * 256 + tid;
        int r = idx >> 4, q = idx & 15;
        int node = row0 + r;
        v[i] = (node < NN) ? x4[(size_t)node * (CIN / 4) + q]
                           : make_float4(0.f, 0.f, 0.f, 0.f);
    }

    for (int c = 0; c < 4; c++) {
        #pragma unroll
        for (int i = 0; i < 8; i++) {
            int idx = i * 256 + tid;
            int r = idx >> 4, q = idx & 15;
            float4 w = v[i];
            __nv_bfloat16 hx = __float2bfloat16_rn(w.x);
            __nv_bfloat16 hy = __float2bfloat16_rn(w.y);
            __nv_bfloat16 hz = __float2bfloat16_rn(w.z);
            __nv_bfloat16 hw = __float2bfloat16_rn(w.w);
            __nv_bfloat16 lx = __float2bfloat16_rn(w.x - __bfloat162float(hx));
            __nv_bfloat16 ly = __float2bfloat16_rn(w.y - __bfloat162float(hy));
            __nv_bfloat16 lz = __float2bfloat16_rn(w.z - __bfloat162float(hz));
            __nv_bfloat16 lw = __float2bfloat16_rn(w.w - __bfloat162float(hw));
            __nv_bfloat162 h01; h01.x = hx; h01.y = hy;
            __nv_bfloat162 h23; h23.x = hz; h23.y = hw;
            __nv_bfloat162 l01; l01.x = lx; l01.y = ly;
            __nv_bfloat162 l23; l23.x = lz; l23.y = lw;
            uint32_t so = swz128((uint32_t)(r * 128 + q * 8));
            *(uint2*)(base + OFF_AHI + so) =
                make_uint2(*(uint32_t*)&h01, *(uint32_t*)&h23);
            *(uint2*)(base + OFF_ALO + so) =
                make_uint2(*(uint32_t*)&l01, *(uint32_t*)&l23);
        }
        #pragma unroll
        for (int i = 0; i < 4; i++) {
            int idx = i * 256 + tid;
            int n = idx >> 3, u = idx & 7;
            uint32_t so = swz128((uint32_t)(n * 128 + u * 16));
            const char* srcH = (const char*)g_WhiT + n * (CIN * 2) + c * 128 + u * 16;
            const char* srcL = (const char*)g_WloT + n * (CIN * 2) + c * 128 + u * 16;
            *(uint4*)(base + OFF_BHI + so) = *(const uint4*)srcH;
            *(uint4*)(base + OFF_BLO + so) = *(const uint4*)srcL;
        }
        __syncthreads();

        if (c < 3) {
            #pragma unroll
            for (int i = 0; i < 8; i++) {
                int idx = i * 256 + tid;
                int r = idx >> 4, q = idx & 15;
                int node = row0 + r;
                v[i] = (node < NN)
                     ? x4[(size_t)node * (CIN / 4) + (c + 1) * 16 + q]
                     : make_float4(0.f, 0.f, 0.f, 0.f);
            }
        }

        #pragma unroll
        for (int ks = 0; ks < 4; ks++) {
            uint32_t ah[2][4], al[2][4];
            #pragma unroll
            for (int mi = 0; mi < 2; mi++) {
                uint32_t r = (uint32_t)(wm * 32 + mi * 16 + (lane & 15));
                uint32_t kb = (uint32_t)(ks * 32 + (lane >> 4) * 16);
                uint32_t so = swz128(r * 128 + kb);
                ldsm_x4(ah[mi], base_u + OFF_AHI + so);
                ldsm_x4(al[mi], base_u + OFF_ALO + so);
            }
            #pragma unroll
            for (int nj2 = 0; nj2 < 4; nj2++) {
                uint32_t n = (uint32_t)(wn * 64 + nj2 * 16 + (lane & 7)
                                        + ((lane >> 4) << 3));
                uint32_t kb = (uint32_t)(ks * 32 + ((lane >> 3) & 1) * 16);
                uint32_t so = swz128(n * 128 + kb);
                uint32_t bh[4], bl[4];
                ldsm_x4(bh, base_u + OFF_BHI + so);
                ldsm_x4(bl, base_u + OFF_BLO + so);
                #pragma unroll
                for (int mi = 0; mi < 2; mi++) {
                    mma_bf16(acc[mi][nj2 * 2 + 0], ah[mi], bh[0], bh[1]);
                    mma_bf16(acc[mi][nj2 * 2 + 1], ah[mi], bh[2], bh[3]);
                    mma_bf16(acc[mi][nj2 * 2 + 0], ah[mi], bl[0], bl[1]);
                    mma_bf16(acc[mi][nj2 * 2 + 1], ah[mi], bl[2], bl[3]);
                    mma_bf16(acc[mi][nj2 * 2 + 0], al[mi], bh[0], bh[1]);
                    mma_bf16(acc[mi][nj2 * 2 + 1], al[mi], bh[2], bh[3]);
                }
            }
        }
        __syncthreads();
    }

    const int group = lane >> 2;
    const int qp    = lane & 3;
    #pragma unroll
    for (int mi = 0; mi < 2; mi++) {
        #pragma unroll
        for (int half = 0; half < 2; half++) {
            int r = wm * 32 + mi * 16 + half * 8 + group;
            int node = row0 + r;
            if (node < NN) {
                float di = g_dinv[node];
                __half* hrow = g_hs16 + (size_t)node * HID;
                #pragma unroll
                for (int nj = 0; nj < 8; nj++) {
                    int col = wn * 64 + nj * 8 + qp * 2;
                    __half2 hh = __floats2half2_rn(
                        acc[mi][nj][half * 2 + 0] * di,
                        acc[mi][nj][half * 2 + 1] * di);
                    *(__half2*)(hrow + col) = hh;
                }
            }
        }
    }
}

// ---------------------------------------------------------------------------
// Aggregate + final linear + log_softmax.  One warp per dst node.
// Gather: lane owns 4 CONTIGUOUS dims -> one LDG.64 per edge row.
// Then 16-shfl transpose to strided ownership for conflict-free sW reads.
// ---------------------------------------------------------------------------
__global__ __launch_bounds__(256) void k_agg_final(const float* __restrict__ bc,
                                                   const float* __restrict__ Wl,
                                                   const float* __restrict__ bl,
                                                   float* __restrict__ out) {
    __shared__ float sW[HID][COUT + 1];
    __shared__ float sBc[HID];
    __shared__ float sBl[COUT];
    for (int i = threadIdx.x; i < HID * COUT; i += 256) {
        int d = i >> 4, c = i & 15;
        sW[d][c] = Wl[i];
    }
    for (int i = threadIdx.x; i < HID; i += 256) sBc[i] = bc[i];
    if (threadIdx.x < COUT) sBl[threadIdx.x] = bl[threadIdx.x];
    __syncthreads();

    const int lane = threadIdx.x & 31;
    const int dst  = (blockIdx.x * blockDim.x + threadIdx.x) >> 5;
    if (dst >= NN) return;

    const int s0 = g_off[dst];
    const int s1 = g_off[dst + 1];
    const float di = g_dinv[dst];
    const uint2* hp = (const uint2*)g_hs16;   // one row = 32 uint2 (4 halves each)

    float a0, a1, a2, a3;   // contiguous dims lane*4 .. lane*4+3
    {
        uint2 u = hp[(size_t)dst * 32 + lane];
        float2 f0 = __half22float2(*(__half2*)&u.x);
        float2 f1 = __half22float2(*(__half2*)&u.y);
        a0 = f0.x; a1 = f0.y; a2 = f1.x; a3 = f1.y;
    }
    for (int b = s0; b < s1; b += 32) {
        int m = s1 - b; if (m > 32) m = 32;
        int s = (lane < m) ? g_esrc[b + lane] : 0;
        #pragma unroll 1
        for (int j = 0; j < m; j++) {
            int ss = __shfl_sync(0xffffffffu, s, j);
            uint2 u = hp[(size_t)ss * 32 + lane];
            float2 f0 = __half22float2(*(__half2*)&u.x);
            float2 f1 = __half22float2(*(__half2*)&u.y);
            a0 += f0.x; a1 += f0.y; a2 += f1.x; a3 += f1.y;
        }
    }

    // transpose: lane l slot t gets dim l + 32t  (from lane 8t + l/4, slot l%4)
    float na[4];
    {
        const int srcbase = lane >> 2;
        const int sl = lane & 3;
        #pragma unroll
        for (int t = 0; t < 4; t++) {
            int srcl = 8 * t + srcbase;
            float v0 = __shfl_sync(0xffffffffu, a0, srcl);
            float v1 = __shfl_sync(0xffffffffu, a1, srcl);
            float v2 = __shfl_sync(0xffffffffu, a2, srcl);
            float v3 = __shfl_sync(0xffffffffu, a3, srcl);
            na[t] = (sl == 0) ? v0 : (sl == 1) ? v1 : (sl == 2) ? v2 : v3;
        }
    }

    na[0] = fmaxf(na[0] * di + sBc[lane],      0.f);
    na[1] = fmaxf(na[1] * di + sBc[lane + 32], 0.f);
    na[2] = fmaxf(na[2] * di + sBc[lane + 64], 0.f);
    na[3] = fmaxf(na[3] * di + sBc[lane + 96], 0.f);

    float p[COUT];
    #pragma unroll
    for (int c = 0; c < COUT; c++) {
        p[c] = na[0] * sW[lane][c] + na[1] * sW[lane + 32][c]
             + na[2] * sW[lane + 64][c] + na[3] * sW[lane + 96][c];
    }
    #pragma unroll
    for (int off = 16; off > 0; off >>= 1)
        #pragma unroll
        for (int c = 0; c < COUT; c++)
            p[c] += __shfl_xor_sync(0xffffffffu, p[c], off);

    #pragma unroll
    for (int c = 0; c < COUT; c++) p[c] += sBl[c];

    float mx = p[0];
    #pragma unroll
    for (int c = 1; c < COUT; c++) mx = fmaxf(mx, p[c]);
    float sum = 0.f;
    #pragma unroll
    for (int c = 0; c < COUT; c++) sum += expf(p[c] - mx);
    float lse = mx + logf(sum);

    if (lane < COUT) out[(size_t)dst * COUT + lane] = p[lane] - lse;
}

// ---------------------------------------------------------------------------
extern "C" void kernel_launch(void* const* d_in, const int* in_sizes, int n_in,
                              void* d_out, int out_size) {
    const float* x      = (const float*)d_in[0];
    const void*  eidx   = d_in[1];
    const float* W_conv = (const float*)d_in[2];
    const float* b_conv = (const float*)d_in[3];
    const float* W_lin  = (const float*)d_in[4];
    const float* b_lin  = (const float*)d_in[5];
    float* out = (float*)d_out;

    cudaFuncSetAttribute(k_gemm_tc, cudaFuncAttributeMaxDynamicSharedMemorySize,
                         SMEM_DYN);

    k_init<<<(NN + 255) / 256, 256>>>((const int*)eidx);
    k_deg<<<1024, 256>>>(eidx);
    k_scanA<<<NBLK, 1024>>>();
    k_scanB<<<1, 128>>>();
    k_scanC<<<(NN + 255) / 256, 256>>>();
    k_sort<<<1024, 256>>>(eidx);
    k_wsplit<<<(CIN * HID + 255) / 256, 256>>>(W_conv);
    k_gemm_tc<<<(NN + 127) / 128, 256, SMEM_DYN>>>(x);
    k_agg_final<<<(NN * 32 + 255) / 256, 256>>>(b_conv, W_lin, b_lin, out);
}

// round 6
// speedup vs baseline: 1.4402x; 1.0614x over previous
#include <cuda_runtime.h>
#include <cuda_bf16.h>
#include <cuda_fp16.h>
#include <math.h>
#include <stdint.h>

#define NN   100000
#define NE   1600000
#define CIN  256
#define HID  128
#define COUT 16
#define NBLK 98          // ceil(NN/1024)

// ---------------- scratch (__device__ globals; no allocs allowed) ----------
__device__ __half          g_hs16[(size_t)(NN + 1) * HID]; // +1 zero row
__device__ int             g_deg[NN];
__device__ float           g_dinv[NN];
__device__ int             g_psc[NN];
__device__ int             g_off[NN + 1];
__device__ int             g_wptr[NN];
__device__ int             g_bsum[NBLK];
__device__ int             g_boff[NBLK];
__device__ int             g_esrc[NE];
__device__ int             g_is64;
__device__ __nv_bfloat16   g_WhiT[HID * CIN];
__device__ __nv_bfloat16   g_WloT[HID * CIN];

__device__ __forceinline__ uint32_t smem_u32(const void* p) {
    uint32_t a;
    asm("{ .reg .u64 t; cvta.to.shared.u64 t, %1; cvt.u32.u64 %0, t; }"
        : "=r"(a) : "l"(p));
    return a;
}
__device__ __forceinline__ uint32_t swz128(uint32_t off) {
    return off ^ ((off >> 3) & 0x70);
}
__device__ __forceinline__ void ldsm_x4(uint32_t* r, uint32_t addr) {
    asm volatile("ldmatrix.sync.aligned.m8n8.x4.shared.b16 {%0,%1,%2,%3}, [%4];"
                 : "=r"(r[0]), "=r"(r[1]), "=r"(r[2]), "=r"(r[3]) : "r"(addr));
}
__device__ __forceinline__ void mma_bf16(float* d, const uint32_t* a,
                                         uint32_t b0, uint32_t b1) {
    asm volatile("mma.sync.aligned.m16n8k16.row.col.f32.bf16.bf16.f32 "
                 "{%0,%1,%2,%3}, {%4,%5,%6,%7}, {%8,%9}, {%0,%1,%2,%3};"
                 : "+f"(d[0]), "+f"(d[1]), "+f"(d[2]), "+f"(d[3])
                 : "r"(a[0]), "r"(a[1]), "r"(a[2]), "r"(a[3]), "r"(b0), "r"(b1));
}
__device__ __forceinline__ uint32_t prmt7632(uint32_t a, uint32_t b) {
    uint32_t r;
    asm("prmt.b32 %0, %1, %2, 0x7632;" : "=r"(r) : "r"(a), "r"(b));
    return r;
}

// ---------------------------------------------------------------------------
// K0 (fused): zero degrees, sniff dtype, split W hi/lo, zero hs16 row NN
// ---------------------------------------------------------------------------
__global__ void k_init(const int* __restrict__ e32, const float* __restrict__ W) {
    int i = blockIdx.x * blockDim.x + threadIdx.x;
    if (i < NN) g_deg[i] = 0;
    if (i < CIN * HID) {
        int k = i >> 7, n = i & 127;
        float w = W[i];
        __nv_bfloat16 hi = __float2bfloat16_rn(w);
        float r = w - __bfloat162float(hi);
        g_WhiT[n * CIN + k] = hi;
        g_WloT[n * CIN + k] = __float2bfloat16_rn(r);
    }
    if (i < 16)
        ((uint4*)(g_hs16 + (size_t)NN * HID))[i] = make_uint4(0u, 0u, 0u, 0u);
    if (i == 0) {
        int is64 = 1;
        #pragma unroll 1
        for (int j = 0; j < 64; j++)
            if (e32[2 * j + 1] != 0) { is64 = 0; break; }
        g_is64 = is64;
    }
}

__global__ void k_deg(const void* __restrict__ eptr) {
    const long long* e64 = (const long long*)eptr;
    const int*       e32 = (const int*)eptr;
    const int is64 = g_is64;
    for (int e = blockIdx.x * blockDim.x + threadIdx.x; e < NE;
         e += gridDim.x * blockDim.x) {
        int d = is64 ? (int)e64[NE + e] : e32[NE + e];
        atomicAdd(&g_deg[d], 1);
    }
}

__global__ __launch_bounds__(1024) void k_scanA() {
    __shared__ int ss[1024];
    const int t = threadIdx.x;
    const int i = blockIdx.x * 1024 + t;
    int v = (i < NN) ? g_deg[i] : 0;
    ss[t] = v;
    __syncthreads();
    #pragma unroll
    for (int off = 1; off < 1024; off <<= 1) {
        int add = (t >= off) ? ss[t - off] : 0;
        __syncthreads();
        ss[t] += add;
        __syncthreads();
    }
    if (i < NN) g_psc[i] = ss[t] - v;
    if (t == 1023) g_bsum[blockIdx.x] = ss[1023];
}

__global__ __launch_bounds__(128) void k_scanB() {
    __shared__ int warp_tot[4];
    const int t = threadIdx.x;
    const int lane = t & 31, w = t >> 5;
    int v = (t < NBLK) ? g_bsum[t] : 0;
    int inc = v;
    #pragma unroll
    for (int off = 1; off < 32; off <<= 1) {
        int up = __shfl_up_sync(0xffffffffu, inc, off);
        if (lane >= off) inc += up;
    }
    if (lane == 31) warp_tot[w] = inc;
    __syncthreads();
    int pre = 0;
    #pragma unroll
    for (int j = 0; j < 4; j++) pre += (j < w) ? warp_tot[j] : 0;
    if (t < NBLK) g_boff[t] = pre + inc - v;
    if (t == 127) g_off[NN] = pre + inc;
}

__global__ void k_scanC() {
    int i = blockIdx.x * blockDim.x + threadIdx.x;
    if (i < NN) {
        int o = g_psc[i] + g_boff[i >> 10];
        g_off[i]  = o;
        g_wptr[i] = o;
        g_dinv[i] = rsqrtf((float)(g_deg[i] + 1));
    }
}

__global__ void k_sort(const void* __restrict__ eptr) {
    const long long* e64 = (const long long*)eptr;
    const int*       e32 = (const int*)eptr;
    const int is64 = g_is64;
    for (int e = blockIdx.x * blockDim.x + threadIdx.x; e < NE;
         e += gridDim.x * blockDim.x) {
        int s = is64 ? (int)e64[e]      : e32[e];
        int d = is64 ? (int)e64[NE + e] : e32[NE + e];
        int pos = atomicAdd(&g_wptr[d], 1);
        g_esrc[pos] = s;
    }
}

// ---------------------------------------------------------------------------
// GEMM: h = x @ W_conv via bf16-split mma.sync (trunc-split x via PRMT)
// ---------------------------------------------------------------------------
#define TILE_B   16384
#define OFF_AHI  0
#define OFF_ALO  16384
#define OFF_BHI  32768
#define OFF_BLO  49152
#define SMEM_DYN (4 * TILE_B + 256)

__global__ __launch_bounds__(256, 2) void k_gemm_tc(const float* __restrict__ x) {
    extern __shared__ char dsm_raw[];
    char* const base = (char*)(((uintptr_t)dsm_raw + 127) & ~(uintptr_t)127);
    const uint32_t base_u = smem_u32(base);

    const int tid  = threadIdx.x;
    const int lane = tid & 31;
    const int wid  = tid >> 5;
    const int wm   = wid & 3;
    const int wn   = wid >> 2;
    const int row0 = blockIdx.x * 128;

    float acc[2][8][4];
    #pragma unroll
    for (int i = 0; i < 2; i++)
        #pragma unroll
        for (int j = 0; j < 8; j++)
            #pragma unroll
            for (int q = 0; q < 4; q++) acc[i][j][q] = 0.f;

    const float4* x4 = (const float4*)x;

    float4 v[8];
    #pragma unroll
    for (int i = 0; i < 8; i++) {
        int idx = i * 256 + tid;
        int r = idx >> 4, q = idx & 15;
        int node = row0 + r;
        v[i] = (node < NN) ? x4[(size_t)node * (CIN / 4) + q]
                           : make_float4(0.f, 0.f, 0.f, 0.f);
    }

    for (int c = 0; c < 4; c++) {
        #pragma unroll
        for (int i = 0; i < 8; i++) {
            int idx = i * 256 + tid;
            int r = idx >> 4, q = idx & 15;
            float4 w = v[i];
            uint32_t b0 = __float_as_uint(w.x), b1 = __float_as_uint(w.y);
            uint32_t b2 = __float_as_uint(w.z), b3 = __float_as_uint(w.w);
            uint32_t hi01 = prmt7632(b0, b1);
            uint32_t hi23 = prmt7632(b2, b3);
            float l0 = w.x - __uint_as_float(b0 & 0xFFFF0000u);
            float l1 = w.y - __uint_as_float(b1 & 0xFFFF0000u);
            float l2 = w.z - __uint_as_float(b2 & 0xFFFF0000u);
            float l3 = w.w - __uint_as_float(b3 & 0xFFFF0000u);
            uint32_t lo01 = prmt7632(__float_as_uint(l0), __float_as_uint(l1));
            uint32_t lo23 = prmt7632(__float_as_uint(l2), __float_as_uint(l3));
            uint32_t so = swz128((uint32_t)(r * 128 + q * 8));
            *(uint2*)(base + OFF_AHI + so) = make_uint2(hi01, hi23);
            *(uint2*)(base + OFF_ALO + so) = make_uint2(lo01, lo23);
        }
        #pragma unroll
        for (int i = 0; i < 4; i++) {
            int idx = i * 256 + tid;
            int n = idx >> 3, u = idx & 7;
            uint32_t so = swz128((uint32_t)(n * 128 + u * 16));
            const char* srcH = (const char*)g_WhiT + n * (CIN * 2) + c * 128 + u * 16;
            const char* srcL = (const char*)g_WloT + n * (CIN * 2) + c * 128 + u * 16;
            *(uint4*)(base + OFF_BHI + so) = *(const uint4*)srcH;
            *(uint4*)(base + OFF_BLO + so) = *(const uint4*)srcL;
        }
        __syncthreads();

        if (c < 3) {
            #pragma unroll
            for (int i = 0; i < 8; i++) {
                int idx = i * 256 + tid;
                int r = idx >> 4, q = idx & 15;
                int node = row0 + r;
                v[i] = (node < NN)
                     ? x4[(size_t)node * (CIN / 4) + (c + 1) * 16 + q]
                     : make_float4(0.f, 0.f, 0.f, 0.f);
            }
        }

        #pragma unroll
        for (int ks = 0; ks < 4; ks++) {
            uint32_t ah[2][4], al[2][4];
            #pragma unroll
            for (int mi = 0; mi < 2; mi++) {
                uint32_t r = (uint32_t)(wm * 32 + mi * 16 + (lane & 15));
                uint32_t kb = (uint32_t)(ks * 32 + (lane >> 4) * 16);
                uint32_t so = swz128(r * 128 + kb);
                ldsm_x4(ah[mi], base_u + OFF_AHI + so);
                ldsm_x4(al[mi], base_u + OFF_ALO + so);
            }
            #pragma unroll
            for (int nj2 = 0; nj2 < 4; nj2++) {
                uint32_t n = (uint32_t)(wn * 64 + nj2 * 16 + (lane & 7)
                                        + ((lane >> 4) << 3));
                uint32_t kb = (uint32_t)(ks * 32 + ((lane >> 3) & 1) * 16);
                uint32_t so = swz128(n * 128 + kb);
                uint32_t bh[4], bl[4];
                ldsm_x4(bh, base_u + OFF_BHI + so);
                ldsm_x4(bl, base_u + OFF_BLO + so);
                #pragma unroll
                for (int mi = 0; mi < 2; mi++) {
                    mma_bf16(acc[mi][nj2 * 2 + 0], ah[mi], bh[0], bh[1]);
                    mma_bf16(acc[mi][nj2 * 2 + 1], ah[mi], bh[2], bh[3]);
                    mma_bf16(acc[mi][nj2 * 2 + 0], ah[mi], bl[0], bl[1]);
                    mma_bf16(acc[mi][nj2 * 2 + 1], ah[mi], bl[2], bl[3]);
                    mma_bf16(acc[mi][nj2 * 2 + 0], al[mi], bh[0], bh[1]);
                    mma_bf16(acc[mi][nj2 * 2 + 1], al[mi], bh[2], bh[3]);
                }
            }
        }
        __syncthreads();
    }

    const int group = lane >> 2;
    const int qp    = lane & 3;
    #pragma unroll
    for (int mi = 0; mi < 2; mi++) {
        #pragma unroll
        for (int half = 0; half < 2; half++) {
            int r = wm * 32 + mi * 16 + half * 8 + group;
            int node = row0 + r;
            if (node < NN) {
                float di = g_dinv[node];
                __half* hrow = g_hs16 + (size_t)node * HID;
                #pragma unroll
                for (int nj = 0; nj < 8; nj++) {
                    int col = wn * 64 + nj * 8 + qp * 2;
                    __half2 hh = __floats2half2_rn(
                        acc[mi][nj][half * 2 + 0] * di,
                        acc[mi][nj][half * 2 + 1] * di);
                    *(__half2*)(hrow + col) = hh;
                }
            }
        }
    }
}

// ---------------------------------------------------------------------------
// Aggregate + final linear + log_softmax.  One warp per dst.
// 2 edges per step (16 lanes x LDG.128 each = one 256B row per half-warp),
// unrolled x2 -> 4 edges / iter, branch-free via zero row NN.
// ---------------------------------------------------------------------------
__global__ __launch_bounds__(256) void k_agg_final(const float* __restrict__ bc,
                                                   const float* __restrict__ Wl,
                                                   const float* __restrict__ bl,
                                                   float* __restrict__ out) {
    __shared__ float sW[HID][COUT + 1];
    __shared__ float sBc[HID];
    __shared__ float sBl[COUT];
    __shared__ float sStage[8][HID];
    for (int i = threadIdx.x; i < HID * COUT; i += 256) {
        int d = i >> 4, c = i & 15;
        sW[d][c] = Wl[i];
    }
    for (int i = threadIdx.x; i < HID; i += 256) sBc[i] = bc[i];
    if (threadIdx.x < COUT) sBl[threadIdx.x] = bl[threadIdx.x];
    __syncthreads();

    const int lane = threadIdx.x & 31;
    const int wblk = threadIdx.x >> 5;
    const int dst  = (blockIdx.x * blockDim.x + threadIdx.x) >> 5;
    if (dst >= NN) return;

    const int s0 = g_off[dst];
    const int s1 = g_off[dst + 1];
    const float di = g_dinv[dst];
    const uint4* hp = (const uint4*)g_hs16;   // row = 16 uint4
    const int seg = lane & 15;
    const int hlf = lane >> 4;

    float a0 = 0.f, a1 = 0.f, a2 = 0.f, a3 = 0.f;
    float a4 = 0.f, a5 = 0.f, a6 = 0.f, a7 = 0.f;

    // self row: half 0 loads dst, half 1 loads zero row
    {
        int ssrc = hlf ? NN : dst;
        uint4 u = hp[(size_t)ssrc * 16 + seg];
        float2 f0 = __half22float2(*(__half2*)&u.x);
        float2 f1 = __half22float2(*(__half2*)&u.y);
        float2 f2 = __half22float2(*(__half2*)&u.z);
        float2 f3 = __half22float2(*(__half2*)&u.w);
        a0 += f0.x; a1 += f0.y; a2 += f1.x; a3 += f1.y;
        a4 += f2.x; a5 += f2.y; a6 += f3.x; a7 += f3.y;
    }

    for (int b = s0; b < s1; b += 32) {
        int m = s1 - b; if (m > 32) m = 32;
        int s = (lane < m) ? __ldg(g_esrc + b + lane) : NN;
        #pragma unroll 1
        for (int j = 0; j < m; j += 4) {
            int p0 = __shfl_sync(0xffffffffu, s, j);
            int p1 = __shfl_sync(0xffffffffu, s, (j + 1) & 31);
            int q0 = __shfl_sync(0xffffffffu, s, (j + 2) & 31);
            int q1 = __shfl_sync(0xffffffffu, s, (j + 3) & 31);
            int srcP = hlf ? p1 : p0;
            int srcQ = hlf ? q1 : q0;
            uint4 u = hp[(size_t)srcP * 16 + seg];
            uint4 w = hp[(size_t)srcQ * 16 + seg];
            float2 f0 = __half22float2(*(__half2*)&u.x);
            float2 f1 = __half22float2(*(__half2*)&u.y);
            float2 f2 = __half22float2(*(__half2*)&u.z);
            float2 f3 = __half22float2(*(__half2*)&u.w);
            float2 g0 = __half22float2(*(__half2*)&w.x);
            float2 g1 = __half22float2(*(__half2*)&w.y);
            float2 g2 = __half22float2(*(__half2*)&w.z);
            float2 g3 = __half22float2(*(__half2*)&w.w);
            a0 += f0.x + g0.x; a1 += f0.y + g0.y;
            a2 += f1.x + g1.x; a3 += f1.y + g1.y;
            a4 += f2.x + g2.x; a5 += f2.y + g2.y;
            a6 += f3.x + g3.x; a7 += f3.y + g3.y;
        }
    }

    // combine halves (both halves end with identical sums)
    a0 += __shfl_xor_sync(0xffffffffu, a0, 16);
    a1 += __shfl_xor_sync(0xffffffffu, a1, 16);
    a2 += __shfl_xor_sync(0xffffffffu, a2, 16);
    a3 += __shfl_xor_sync(0xffffffffu, a3, 16);
    a4 += __shfl_xor_sync(0xffffffffu, a4, 16);
    a5 += __shfl_xor_sync(0xffffffffu, a5, 16);
    a6 += __shfl_xor_sync(0xffffffffu, a6, 16);
    a7 += __shfl_xor_sync(0xffffffffu, a7, 16);

    // stage dims (seg*8 .. seg*8+7) -> smem, re-read strided
    if (hlf == 0) {
        float* st = &sStage[wblk][seg * 8];
        st[0] = a0; st[1] = a1; st[2] = a2; st[3] = a3;
        st[4] = a4; st[5] = a5; st[6] = a6; st[7] = a7;
    }
    __syncwarp();

    float na[4];
    #pragma unroll
    for (int t = 0; t < 4; t++) {
        float v = sStage[wblk][lane + 32 * t];
        na[t] = fmaxf(v * di + sBc[lane + 32 * t], 0.f);
    }

    float p[COUT];
    #pragma unroll
    for (int c = 0; c < COUT; c++) {
        p[c] = na[0] * sW[lane][c] + na[1] * sW[lane + 32][c]
             + na[2] * sW[lane + 64][c] + na[3] * sW[lane + 96][c];
    }
    #pragma unroll
    for (int off = 16; off > 0; off >>= 1)
        #pragma unroll
        for (int c = 0; c < COUT; c++)
            p[c] += __shfl_xor_sync(0xffffffffu, p[c], off);

    #pragma unroll
    for (int c = 0; c < COUT; c++) p[c] += sBl[c];

    float mx = p[0];
    #pragma unroll
    for (int c = 1; c < COUT; c++) mx = fmaxf(mx, p[c]);
    float sum = 0.f;
    #pragma unroll
    for (int c = 0; c < COUT; c++) sum += expf(p[c] - mx);
    float lse = mx + logf(sum);

    if (lane < COUT) out[(size_t)dst * COUT + lane] = p[lane] - lse;
}

// ---------------------------------------------------------------------------
extern "C" void kernel_launch(void* const* d_in, const int* in_sizes, int n_in,
                              void* d_out, int out_size) {
    const float* x      = (const float*)d_in[0];
    const void*  eidx   = d_in[1];
    const float* W_conv = (const float*)d_in[2];
    const float* b_conv = (const float*)d_in[3];
    const float* W_lin  = (const float*)d_in[4];
    const float* b_lin  = (const float*)d_in[5];
    float* out = (float*)d_out;

    cudaFuncSetAttribute(k_gemm_tc, cudaFuncAttributeMaxDynamicSharedMemorySize,
                         SMEM_DYN);

    k_init<<<(NN + 255) / 256, 256>>>((const int*)eidx, W_conv);
    k_deg<<<1024, 256>>>(eidx);
    k_scanA<<<NBLK, 1024>>>();
    k_scanB<<<1, 128>>>();
    k_scanC<<<(NN + 255) / 256, 256>>>();
    k_sort<<<1024, 256>>>(eidx);
    k_gemm_tc<<<(NN + 127) / 128, 256, SMEM_DYN>>>(x);
    k_agg_final<<<(NN * 32 + 255) / 256, 256>>>(b_conv, W_lin, b_lin, out);
}

// round 7
// speedup vs baseline: 1.5769x; 1.0949x over previous
#include <cuda_runtime.h>
#include <cuda_bf16.h>
#include <cuda_fp16.h>
#include <math.h>
#include <stdint.h>

#define NN   100000
#define NE   1600000
#define CIN  256
#define HID  128
#define COUT 16
#define NBLK 98          // ceil(NN/1024)

// ---------------- scratch (__device__ globals; no allocs allowed) ----------
__device__ __half          g_hs16[(size_t)(NN + 1) * HID]; // raw h, +1 zero row
__device__ int             g_deg[NN];
__device__ float           g_dinv[NN];
__device__ int             g_psc[NN];
__device__ int             g_off[NN + 1];
__device__ int             g_wptr[NN];
__device__ int             g_bsum[NBLK];
__device__ int             g_boff[NBLK];
__device__ int             g_esrc[NE];
__device__ int             g_is64;
__device__ __nv_bfloat16   g_WhiT[HID * CIN];
__device__ __nv_bfloat16   g_WloT[HID * CIN];

__device__ __forceinline__ uint32_t smem_u32(const void* p) {
    uint32_t a;
    asm("{ .reg .u64 t; cvta.to.shared.u64 t, %1; cvt.u32.u64 %0, t; }"
        : "=r"(a) : "l"(p));
    return a;
}
__device__ __forceinline__ uint32_t swz128(uint32_t off) {
    return off ^ ((off >> 3) & 0x70);
}
__device__ __forceinline__ void ldsm_x4(uint32_t* r, uint32_t addr) {
    asm volatile("ldmatrix.sync.aligned.m8n8.x4.shared.b16 {%0,%1,%2,%3}, [%4];"
                 : "=r"(r[0]), "=r"(r[1]), "=r"(r[2]), "=r"(r[3]) : "r"(addr));
}
__device__ __forceinline__ void mma_bf16(float* d, const uint32_t* a,
                                         uint32_t b0, uint32_t b1) {
    asm volatile("mma.sync.aligned.m16n8k16.row.col.f32.bf16.bf16.f32 "
                 "{%0,%1,%2,%3}, {%4,%5,%6,%7}, {%8,%9}, {%0,%1,%2,%3};"
                 : "+f"(d[0]), "+f"(d[1]), "+f"(d[2]), "+f"(d[3])
                 : "r"(a[0]), "r"(a[1]), "r"(a[2]), "r"(a[3]), "r"(b0), "r"(b1));
}
__device__ __forceinline__ uint32_t prmt7632(uint32_t a, uint32_t b) {
    uint32_t r;
    asm("prmt.b32 %0, %1, %2, 0x7632;" : "=r"(r) : "r"(a), "r"(b));
    return r;
}

// ---------------------------------------------------------------------------
// K0 (fused): zero degrees, sniff dtype, split W hi/lo, zero hs16 row NN
// ---------------------------------------------------------------------------
__global__ void k_init(const int* __restrict__ e32, const float* __restrict__ W) {
    int i = blockIdx.x * blockDim.x + threadIdx.x;
    if (i < NN) g_deg[i] = 0;
    if (i < CIN * HID) {
        int k = i >> 7, n = i & 127;
        float w = W[i];
        __nv_bfloat16 hi = __float2bfloat16_rn(w);
        float r = w - __bfloat162float(hi);
        g_WhiT[n * CIN + k] = hi;
        g_WloT[n * CIN + k] = __float2bfloat16_rn(r);
    }
    if (i < 16)
        ((uint4*)(g_hs16 + (size_t)NN * HID))[i] = make_uint4(0u, 0u, 0u, 0u);
    if (i == 0) {
        int is64 = 1;
        #pragma unroll 1
        for (int j = 0; j < 64; j++)
            if (e32[2 * j + 1] != 0) { is64 = 0; break; }
        g_is64 = is64;
    }
}

__global__ void k_deg(const void* __restrict__ eptr) {
    const long long* e64 = (const long long*)eptr;
    const int*       e32 = (const int*)eptr;
    const int is64 = g_is64;
    for (int e = blockIdx.x * blockDim.x + threadIdx.x; e < NE;
         e += gridDim.x * blockDim.x) {
        int d = is64 ? (int)e64[NE + e] : e32[NE + e];
        atomicAdd(&g_deg[d], 1);
    }
}

__global__ __launch_bounds__(1024) void k_scanA() {
    __shared__ int ss[1024];
    const int t = threadIdx.x;
    const int i = blockIdx.x * 1024 + t;
    int v = (i < NN) ? g_deg[i] : 0;
    ss[t] = v;
    __syncthreads();
    #pragma unroll
    for (int off = 1; off < 1024; off <<= 1) {
        int add = (t >= off) ? ss[t - off] : 0;
        __syncthreads();
        ss[t] += add;
        __syncthreads();
    }
    if (i < NN) g_psc[i] = ss[t] - v;
    if (t == 1023) g_bsum[blockIdx.x] = ss[1023];
}

__global__ __launch_bounds__(128) void k_scanB() {
    __shared__ int warp_tot[4];
    const int t = threadIdx.x;
    const int lane = t & 31, w = t >> 5;
    int v = (t < NBLK) ? g_bsum[t] : 0;
    int inc = v;
    #pragma unroll
    for (int off = 1; off < 32; off <<= 1) {
        int up = __shfl_up_sync(0xffffffffu, inc, off);
        if (lane >= off) inc += up;
    }
    if (lane == 31) warp_tot[w] = inc;
    __syncthreads();
    int pre = 0;
    #pragma unroll
    for (int j = 0; j < 4; j++) pre += (j < w) ? warp_tot[j] : 0;
    if (t < NBLK) g_boff[t] = pre + inc - v;
    if (t == 127) g_off[NN] = pre + inc;
}

__global__ void k_scanC() {
    int i = blockIdx.x * blockDim.x + threadIdx.x;
    if (i < NN) {
        int o = g_psc[i] + g_boff[i >> 10];
        g_off[i]  = o;
        g_wptr[i] = o;
        g_dinv[i] = rsqrtf((float)(g_deg[i] + 1));
    }
}

__global__ void k_sort(const void* __restrict__ eptr) {
    const long long* e64 = (const long long*)eptr;
    const int*       e32 = (const int*)eptr;
    const int is64 = g_is64;
    for (int e = blockIdx.x * blockDim.x + threadIdx.x; e < NE;
         e += gridDim.x * blockDim.x) {
        int s = is64 ? (int)e64[e]      : e32[e];
        int d = is64 ? (int)e64[NE + e] : e32[NE + e];
        int pos = atomicAdd(&g_wptr[d], 1);
        g_esrc[pos] = s;
    }
}

// ---------------------------------------------------------------------------
// GEMM: h = x @ W_conv via bf16-split mma.sync (trunc-split x via PRMT).
// Epilogue stores RAW h (fp16) — no dinv dependency => overlaps edge prep.
// ---------------------------------------------------------------------------
#define TILE_B   16384
#define OFF_AHI  0
#define OFF_ALO  16384
#define OFF_BHI  32768
#define OFF_BLO  49152
#define SMEM_DYN (4 * TILE_B + 256)

__global__ __launch_bounds__(256, 2) void k_gemm_tc(const float* __restrict__ x) {
    extern __shared__ char dsm_raw[];
    char* const base = (char*)(((uintptr_t)dsm_raw + 127) & ~(uintptr_t)127);
    const uint32_t base_u = smem_u32(base);

    const int tid  = threadIdx.x;
    const int lane = tid & 31;
    const int wid  = tid >> 5;
    const int wm   = wid & 3;
    const int wn   = wid >> 2;
    const int row0 = blockIdx.x * 128;

    float acc[2][8][4];
    #pragma unroll
    for (int i = 0; i < 2; i++)
        #pragma unroll
        for (int j = 0; j < 8; j++)
            #pragma unroll
            for (int q = 0; q < 4; q++) acc[i][j][q] = 0.f;

    const float4* x4 = (const float4*)x;

    float4 v[8];
    #pragma unroll
    for (int i = 0; i < 8; i++) {
        int idx = i * 256 + tid;
        int r = idx >> 4, q = idx & 15;
        int node = row0 + r;
        v[i] = (node < NN) ? x4[(size_t)node * (CIN / 4) + q]
                           : make_float4(0.f, 0.f, 0.f, 0.f);
    }

    for (int c = 0; c < 4; c++) {
        #pragma unroll
        for (int i = 0; i < 8; i++) {
            int idx = i * 256 + tid;
            int r = idx >> 4, q = idx & 15;
            float4 w = v[i];
            uint32_t b0 = __float_as_uint(w.x), b1 = __float_as_uint(w.y);
            uint32_t b2 = __float_as_uint(w.z), b3 = __float_as_uint(w.w);
            uint32_t hi01 = prmt7632(b0, b1);
            uint32_t hi23 = prmt7632(b2, b3);
            float l0 = w.x - __uint_as_float(b0 & 0xFFFF0000u);
            float l1 = w.y - __uint_as_float(b1 & 0xFFFF0000u);
            float l2 = w.z - __uint_as_float(b2 & 0xFFFF0000u);
            float l3 = w.w - __uint_as_float(b3 & 0xFFFF0000u);
            uint32_t lo01 = prmt7632(__float_as_uint(l0), __float_as_uint(l1));
            uint32_t lo23 = prmt7632(__float_as_uint(l2), __float_as_uint(l3));
            uint32_t so = swz128((uint32_t)(r * 128 + q * 8));
            *(uint2*)(base + OFF_AHI + so) = make_uint2(hi01, hi23);
            *(uint2*)(base + OFF_ALO + so) = make_uint2(lo01, lo23);
        }
        #pragma unroll
        for (int i = 0; i < 4; i++) {
            int idx = i * 256 + tid;
            int n = idx >> 3, u = idx & 7;
            uint32_t so = swz128((uint32_t)(n * 128 + u * 16));
            const char* srcH = (const char*)g_WhiT + n * (CIN * 2) + c * 128 + u * 16;
            const char* srcL = (const char*)g_WloT + n * (CIN * 2) + c * 128 + u * 16;
            *(uint4*)(base + OFF_BHI + so) = *(const uint4*)srcH;
            *(uint4*)(base + OFF_BLO + so) = *(const uint4*)srcL;
        }
        __syncthreads();

        if (c < 3) {
            #pragma unroll
            for (int i = 0; i < 8; i++) {
                int idx = i * 256 + tid;
                int r = idx >> 4, q = idx & 15;
                int node = row0 + r;
                v[i] = (node < NN)
                     ? x4[(size_t)node * (CIN / 4) + (c + 1) * 16 + q]
                     : make_float4(0.f, 0.f, 0.f, 0.f);
            }
        }

        #pragma unroll
        for (int ks = 0; ks < 4; ks++) {
            uint32_t ah[2][4], al[2][4];
            #pragma unroll
            for (int mi = 0; mi < 2; mi++) {
                uint32_t r = (uint32_t)(wm * 32 + mi * 16 + (lane & 15));
                uint32_t kb = (uint32_t)(ks * 32 + (lane >> 4) * 16);
                uint32_t so = swz128(r * 128 + kb);
                ldsm_x4(ah[mi], base_u + OFF_AHI + so);
                ldsm_x4(al[mi], base_u + OFF_ALO + so);
            }
            #pragma unroll
            for (int nj2 = 0; nj2 < 4; nj2++) {
                uint32_t n = (uint32_t)(wn * 64 + nj2 * 16 + (lane & 7)
                                        + ((lane >> 4) << 3));
                uint32_t kb = (uint32_t)(ks * 32 + ((lane >> 3) & 1) * 16);
                uint32_t so = swz128(n * 128 + kb);
                uint32_t bh[4], bl[4];
                ldsm_x4(bh, base_u + OFF_BHI + so);
                ldsm_x4(bl, base_u + OFF_BLO + so);
                #pragma unroll
                for (int mi = 0; mi < 2; mi++) {
                    mma_bf16(acc[mi][nj2 * 2 + 0], ah[mi], bh[0], bh[1]);
                    mma_bf16(acc[mi][nj2 * 2 + 1], ah[mi], bh[2], bh[3]);
                    mma_bf16(acc[mi][nj2 * 2 + 0], ah[mi], bl[0], bl[1]);
                    mma_bf16(acc[mi][nj2 * 2 + 1], ah[mi], bl[2], bl[3]);
                    mma_bf16(acc[mi][nj2 * 2 + 0], al[mi], bh[0], bh[1]);
                    mma_bf16(acc[mi][nj2 * 2 + 1], al[mi], bh[2], bh[3]);
                }
            }
        }
        __syncthreads();
    }

    const int group = lane >> 2;
    const int qp    = lane & 3;
    #pragma unroll
    for (int mi = 0; mi < 2; mi++) {
        #pragma unroll
        for (int half = 0; half < 2; half++) {
            int r = wm * 32 + mi * 16 + half * 8 + group;
            int node = row0 + r;
            if (node < NN) {
                __half* hrow = g_hs16 + (size_t)node * HID;
                #pragma unroll
                for (int nj = 0; nj < 8; nj++) {
                    int col = wn * 64 + nj * 8 + qp * 2;
                    __half2 hh = __floats2half2_rn(
                        acc[mi][nj][half * 2 + 0],
                        acc[mi][nj][half * 2 + 1]);
                    *(__half2*)(hrow + col) = hh;
                }
            }
        }
    }
}

// ---------------------------------------------------------------------------
// Aggregate + final linear + log_softmax.  One warp per dst.
// hs16 holds raw h; per-src dinv applied at gather via shfl-broadcast FMA.
// ---------------------------------------------------------------------------
__global__ __launch_bounds__(256) void k_agg_final(const float* __restrict__ bc,
                                                   const float* __restrict__ Wl,
                                                   const float* __restrict__ bl,
                                                   float* __restrict__ out) {
    __shared__ float sW[HID][COUT + 1];
    __shared__ float sBc[HID];
    __shared__ float sBl[COUT];
    __shared__ float sStage[8][HID];
    for (int i = threadIdx.x; i < HID * COUT; i += 256) {
        int d = i >> 4, c = i & 15;
        sW[d][c] = Wl[i];
    }
    for (int i = threadIdx.x; i < HID; i += 256) sBc[i] = bc[i];
    if (threadIdx.x < COUT) sBl[threadIdx.x] = bl[threadIdx.x];
    __syncthreads();

    const int lane = threadIdx.x & 31;
    const int wblk = threadIdx.x >> 5;
    const int dst  = (blockIdx.x * blockDim.x + threadIdx.x) >> 5;
    if (dst >= NN) return;

    const int s0 = g_off[dst];
    const int s1 = g_off[dst + 1];
    const float di = g_dinv[dst];
    const uint4* hp = (const uint4*)g_hs16;
    const int seg = lane & 15;
    const int hlf = lane >> 4;

    float a0, a1, a2, a3, a4, a5, a6, a7;
    {   // self row: half 0 dst row with coeff di, half 1 zero row
        int ssrc = hlf ? NN : dst;
        float cf = hlf ? 0.f : di;
        uint4 u = hp[(size_t)ssrc * 16 + seg];
        float2 f0 = __half22float2(*(__half2*)&u.x);
        float2 f1 = __half22float2(*(__half2*)&u.y);
        float2 f2 = __half22float2(*(__half2*)&u.z);
        float2 f3 = __half22float2(*(__half2*)&u.w);
        a0 = f0.x * cf; a1 = f0.y * cf; a2 = f1.x * cf; a3 = f1.y * cf;
        a4 = f2.x * cf; a5 = f2.y * cf; a6 = f3.x * cf; a7 = f3.y * cf;
    }

    for (int b = s0; b < s1; b += 32) {
        int m = s1 - b; if (m > 32) m = 32;
        int   s  = (lane < m) ? __ldg(g_esrc + b + lane) : NN;
        float ds = (lane < m) ? __ldg(g_dinv + s) : 0.f;
        #pragma unroll 1
        for (int j = 0; j < m; j += 4) {
            int   p0 = __shfl_sync(0xffffffffu, s,  j);
            int   p1 = __shfl_sync(0xffffffffu, s,  j + 1);
            int   q0 = __shfl_sync(0xffffffffu, s,  j + 2);
            int   q1 = __shfl_sync(0xffffffffu, s,  j + 3);
            float e0 = __shfl_sync(0xffffffffu, ds, j);
            float e1 = __shfl_sync(0xffffffffu, ds, j + 1);
            float e2 = __shfl_sync(0xffffffffu, ds, j + 2);
            float e3 = __shfl_sync(0xffffffffu, ds, j + 3);
            int   srcP = hlf ? p1 : p0;
            int   srcQ = hlf ? q1 : q0;
            float dp   = hlf ? e1 : e0;
            float dq   = hlf ? e3 : e2;
            uint4 u = hp[(size_t)srcP * 16 + seg];
            uint4 w = hp[(size_t)srcQ * 16 + seg];
            float2 f0 = __half22float2(*(__half2*)&u.x);
            float2 f1 = __half22float2(*(__half2*)&u.y);
            float2 f2 = __half22float2(*(__half2*)&u.z);
            float2 f3 = __half22float2(*(__half2*)&u.w);
            float2 g0 = __half22float2(*(__half2*)&w.x);
            float2 g1 = __half22float2(*(__half2*)&w.y);
            float2 g2 = __half22float2(*(__half2*)&w.z);
            float2 g3 = __half22float2(*(__half2*)&w.w);
            a0 = fmaf(f0.x, dp, fmaf(g0.x, dq, a0));
            a1 = fmaf(f0.y, dp, fmaf(g0.y, dq, a1));
            a2 = fmaf(f1.x, dp, fmaf(g1.x, dq, a2));
            a3 = fmaf(f1.y, dp, fmaf(g1.y, dq, a3));
            a4 = fmaf(f2.x, dp, fmaf(g2.x, dq, a4));
            a5 = fmaf(f2.y, dp, fmaf(g2.y, dq, a5));
            a6 = fmaf(f3.x, dp, fmaf(g3.x, dq, a6));
            a7 = fmaf(f3.y, dp, fmaf(g3.y, dq, a7));
        }
    }

    a0 += __shfl_xor_sync(0xffffffffu, a0, 16);
    a1 += __shfl_xor_sync(0xffffffffu, a1, 16);
    a2 += __shfl_xor_sync(0xffffffffu, a2, 16);
    a3 += __shfl_xor_sync(0xffffffffu, a3, 16);
    a4 += __shfl_xor_sync(0xffffffffu, a4, 16);
    a5 += __shfl_xor_sync(0xffffffffu, a5, 16);
    a6 += __shfl_xor_sync(0xffffffffu, a6, 16);
    a7 += __shfl_xor_sync(0xffffffffu, a7, 16);

    if (hlf == 0) {
        float* st = &sStage[wblk][seg * 8];
        st[0] = a0; st[1] = a1; st[2] = a2; st[3] = a3;
        st[4] = a4; st[5] = a5; st[6] = a6; st[7] = a7;
    }
    __syncwarp();

    float na[4];
    #pragma unroll
    for (int t = 0; t < 4; t++) {
        float v = sStage[wblk][lane + 32 * t];
        na[t] = fmaxf(v * di + sBc[lane + 32 * t], 0.f);
    }

    float p[COUT];
    #pragma unroll
    for (int c = 0; c < COUT; c++) {
        p[c] = na[0] * sW[lane][c] + na[1] * sW[lane + 32][c]
             + na[2] * sW[lane + 64][c] + na[3] * sW[lane + 96][c];
    }
    #pragma unroll
    for (int off = 16; off > 0; off >>= 1)
        #pragma unroll
        for (int c = 0; c < COUT; c++)
            p[c] += __shfl_xor_sync(0xffffffffu, p[c], off);

    #pragma unroll
    for (int c = 0; c < COUT; c++) p[c] += sBl[c];

    float mx = p[0];
    #pragma unroll
    for (int c = 1; c < COUT; c++) mx = fmaxf(mx, p[c]);
    float sum = 0.f;
    #pragma unroll
    for (int c = 0; c < COUT; c++) sum += expf(p[c] - mx);
    float lse = mx + logf(sum);

    if (lane < COUT) out[(size_t)dst * COUT + lane] = p[lane] - lse;
}

// ---------------------------------------------------------------------------
extern "C" void kernel_launch(void* const* d_in, const int* in_sizes, int n_in,
                              void* d_out, int out_size) {
    const float* x      = (const float*)d_in[0];
    const void*  eidx   = d_in[1];
    const float* W_conv = (const float*)d_in[2];
    const float* b_conv = (const float*)d_in[3];
    const float* W_lin  = (const float*)d_in[4];
    const float* b_lin  = (const float*)d_in[5];
    float* out = (float*)d_out;

    // one-time handle creation (idempotent; identical launch set every call)
    static cudaStream_t s_side = nullptr;
    static cudaEvent_t  ev_fork = nullptr, ev_join = nullptr;
    if (s_side == nullptr) {
        cudaStreamCreateWithFlags(&s_side, cudaStreamNonBlocking);
        cudaEventCreateWithFlags(&ev_fork, cudaEventDisableTiming);
        cudaEventCreateWithFlags(&ev_join, cudaEventDisableTiming);
        cudaFuncSetAttribute(k_gemm_tc,
                             cudaFuncAttributeMaxDynamicSharedMemorySize,
                             SMEM_DYN);
    }

    k_init<<<(NN + 255) / 256, 256>>>((const int*)eidx, W_conv);

    // fork: edge preprocessing on side stream
    cudaEventRecord(ev_fork, 0);
    cudaStreamWaitEvent(s_side, ev_fork, 0);
    k_deg<<<1024, 256, 0, s_side>>>(eidx);
    k_scanA<<<NBLK, 1024, 0, s_side>>>();
    k_scanB<<<1, 128, 0, s_side>>>();
    k_scanC<<<(NN + 255) / 256, 256, 0, s_side>>>();
    k_sort<<<1024, 256, 0, s_side>>>(eidx);
    cudaEventRecord(ev_join, s_side);

    // main stream: GEMM runs concurrently with preprocessing
    k_gemm_tc<<<(NN + 127) / 128, 256, SMEM_DYN>>>(x);

    // join, then aggregate + final
    cudaStreamWaitEvent(0, ev_join, 0);
    k_agg_final<<<(NN * 32 + 255) / 256, 256>>>(b_conv, W_lin, b_lin, out);
}

// round 8
// speedup vs baseline: 1.5775x; 1.0004x over previous
#include <cuda_runtime.h>
#include <cuda_bf16.h>
#include <cuda_fp16.h>
#include <math.h>
#include <stdint.h>

#define NN   100000
#define NE   1600000
#define CIN  256
#define HID  128
#define COUT 16
#define NBLK 98          // ceil(NN/1024)

// ---------------- scratch (__device__ globals; no allocs allowed) ----------
__device__ __half          g_hs16[(size_t)(NN + 1) * HID]; // raw h, +1 zero row
__device__ int             g_deg[NN];
__device__ float           g_dinv[NN];
__device__ int             g_psc[NN];
__device__ int             g_off[NN + 1];
__device__ int             g_wptr[NN];
__device__ int             g_bsum[NBLK];
__device__ int             g_boff[NBLK];
__device__ int             g_esrc[NE];
__device__ int             g_is64;
__device__ __nv_bfloat16   g_WhiT[HID * CIN];
__device__ __nv_bfloat16   g_WloT[HID * CIN];

__device__ __forceinline__ uint32_t smem_u32(const void* p) {
    uint32_t a;
    asm("{ .reg .u64 t; cvta.to.shared.u64 t, %1; cvt.u32.u64 %0, t; }"
        : "=r"(a) : "l"(p));
    return a;
}
__device__ __forceinline__ uint32_t swz128(uint32_t off) {
    return off ^ ((off >> 3) & 0x70);
}
__device__ __forceinline__ void ldsm_x4(uint32_t* r, uint32_t addr) {
    asm volatile("ldmatrix.sync.aligned.m8n8.x4.shared.b16 {%0,%1,%2,%3}, [%4];"
                 : "=r"(r[0]), "=r"(r[1]), "=r"(r[2]), "=r"(r[3]) : "r"(addr));
}
__device__ __forceinline__ void mma_bf16(float* d, const uint32_t* a,
                                         uint32_t b0, uint32_t b1) {
    asm volatile("mma.sync.aligned.m16n8k16.row.col.f32.bf16.bf16.f32 "
                 "{%0,%1,%2,%3}, {%4,%5,%6,%7}, {%8,%9}, {%0,%1,%2,%3};"
                 : "+f"(d[0]), "+f"(d[1]), "+f"(d[2]), "+f"(d[3])
                 : "r"(a[0]), "r"(a[1]), "r"(a[2]), "r"(a[3]), "r"(b0), "r"(b1));
}
__device__ __forceinline__ uint32_t prmt7632(uint32_t a, uint32_t b) {
    uint32_t r;
    asm("prmt.b32 %0, %1, %2, 0x7632;" : "=r"(r) : "r"(a), "r"(b));
    return r;
}

// ---------------------------------------------------------------------------
// K0 (fused): zero degrees, sniff dtype, split W hi/lo, zero hs16 row NN
// ---------------------------------------------------------------------------
__global__ void k_init(const int* __restrict__ e32, const float* __restrict__ W) {
    int i = blockIdx.x * blockDim.x + threadIdx.x;
    if (i < NN) g_deg[i] = 0;
    if (i < CIN * HID) {
        int k = i >> 7, n = i & 127;
        float w = W[i];
        __nv_bfloat16 hi = __float2bfloat16_rn(w);
        float r = w - __bfloat162float(hi);
        g_WhiT[n * CIN + k] = hi;
        g_WloT[n * CIN + k] = __float2bfloat16_rn(r);
    }
    if (i < 16)
        ((uint4*)(g_hs16 + (size_t)NN * HID))[i] = make_uint4(0u, 0u, 0u, 0u);
    if (i == 0) {
        int is64 = 1;
        #pragma unroll 1
        for (int j = 0; j < 64; j++)
            if (e32[2 * j + 1] != 0) { is64 = 0; break; }
        g_is64 = is64;
    }
}

__global__ void k_deg(const void* __restrict__ eptr) {
    const long long* e64 = (const long long*)eptr;
    const int*       e32 = (const int*)eptr;
    const int is64 = g_is64;
    for (int e = blockIdx.x * blockDim.x + threadIdx.x; e < NE;
         e += gridDim.x * blockDim.x) {
        int d = is64 ? (int)e64[NE + e] : e32[NE + e];
        atomicAdd(&g_deg[d], 1);
    }
}

__global__ __launch_bounds__(1024) void k_scanA() {
    __shared__ int ss[1024];
    const int t = threadIdx.x;
    const int i = blockIdx.x * 1024 + t;
    int v = (i < NN) ? g_deg[i] : 0;
    ss[t] = v;
    __syncthreads();
    #pragma unroll
    for (int off = 1; off < 1024; off <<= 1) {
        int add = (t >= off) ? ss[t - off] : 0;
        __syncthreads();
        ss[t] += add;
        __syncthreads();
    }
    if (i < NN) g_psc[i] = ss[t] - v;
    if (t == 1023) g_bsum[blockIdx.x] = ss[1023];
}

__global__ __launch_bounds__(128) void k_scanB() {
    __shared__ int warp_tot[4];
    const int t = threadIdx.x;
    const int lane = t & 31, w = t >> 5;
    int v = (t < NBLK) ? g_bsum[t] : 0;
    int inc = v;
    #pragma unroll
    for (int off = 1; off < 32; off <<= 1) {
        int up = __shfl_up_sync(0xffffffffu, inc, off);
        if (lane >= off) inc += up;
    }
    if (lane == 31) warp_tot[w] = inc;
    __syncthreads();
    int pre = 0;
    #pragma unroll
    for (int j = 0; j < 4; j++) pre += (j < w) ? warp_tot[j] : 0;
    if (t < NBLK) g_boff[t] = pre + inc - v;
    if (t == 127) g_off[NN] = pre + inc;
}

__global__ void k_scanC() {
    int i = blockIdx.x * blockDim.x + threadIdx.x;
    if (i < NN) {
        int o = g_psc[i] + g_boff[i >> 10];
        g_off[i]  = o;
        g_wptr[i] = o;
        g_dinv[i] = rsqrtf((float)(g_deg[i] + 1));
    }
}

__global__ void k_sort(const void* __restrict__ eptr) {
    const long long* e64 = (const long long*)eptr;
    const int*       e32 = (const int*)eptr;
    const int is64 = g_is64;
    for (int e = blockIdx.x * blockDim.x + threadIdx.x; e < NE;
         e += gridDim.x * blockDim.x) {
        int s = is64 ? (int)e64[e]      : e32[e];
        int d = is64 ? (int)e64[NE + e] : e32[NE + e];
        int pos = atomicAdd(&g_wptr[d], 1);
        g_esrc[pos] = s;
    }
}

// ---------------------------------------------------------------------------
// GEMM: h = x @ W_conv via bf16-split mma.sync (trunc-split x via PRMT).
// Epilogue stores RAW h (fp16) — no dinv dependency => overlaps edge prep.
// ---------------------------------------------------------------------------
#define TILE_B   16384
#define OFF_AHI  0
#define OFF_ALO  16384
#define OFF_BHI  32768
#define OFF_BLO  49152
#define SMEM_DYN (4 * TILE_B + 256)

__global__ __launch_bounds__(256, 2) void k_gemm_tc(const float* __restrict__ x) {
    extern __shared__ char dsm_raw[];
    char* const base = (char*)(((uintptr_t)dsm_raw + 127) & ~(uintptr_t)127);
    const uint32_t base_u = smem_u32(base);

    const int tid  = threadIdx.x;
    const int lane = tid & 31;
    const int wid  = tid >> 5;
    const int wm   = wid & 3;
    const int wn   = wid >> 2;
    const int row0 = blockIdx.x * 128;

    float acc[2][8][4];
    #pragma unroll
    for (int i = 0; i < 2; i++)
        #pragma unroll
        for (int j = 0; j < 8; j++)
            #pragma unroll
            for (int q = 0; q < 4; q++) acc[i][j][q] = 0.f;

    const float4* x4 = (const float4*)x;

    float4 v[8];
    #pragma unroll
    for (int i = 0; i < 8; i++) {
        int idx = i * 256 + tid;
        int r = idx >> 4, q = idx & 15;
        int node = row0 + r;
        v[i] = (node < NN) ? x4[(size_t)node * (CIN / 4) + q]
                           : make_float4(0.f, 0.f, 0.f, 0.f);
    }

    for (int c = 0; c < 4; c++) {
        #pragma unroll
        for (int i = 0; i < 8; i++) {
            int idx = i * 256 + tid;
            int r = idx >> 4, q = idx & 15;
            float4 w = v[i];
            uint32_t b0 = __float_as_uint(w.x), b1 = __float_as_uint(w.y);
            uint32_t b2 = __float_as_uint(w.z), b3 = __float_as_uint(w.w);
            uint32_t hi01 = prmt7632(b0, b1);
            uint32_t hi23 = prmt7632(b2, b3);
            float l0 = w.x - __uint_as_float(b0 & 0xFFFF0000u);
            float l1 = w.y - __uint_as_float(b1 & 0xFFFF0000u);
            float l2 = w.z - __uint_as_float(b2 & 0xFFFF0000u);
            float l3 = w.w - __uint_as_float(b3 & 0xFFFF0000u);
            uint32_t lo01 = prmt7632(__float_as_uint(l0), __float_as_uint(l1));
            uint32_t lo23 = prmt7632(__float_as_uint(l2), __float_as_uint(l3));
            uint32_t so = swz128((uint32_t)(r * 128 + q * 8));
            *(uint2*)(base + OFF_AHI + so) = make_uint2(hi01, hi23);
            *(uint2*)(base + OFF_ALO + so) = make_uint2(lo01, lo23);
        }
        #pragma unroll
        for (int i = 0; i < 4; i++) {
            int idx = i * 256 + tid;
            int n = idx >> 3, u = idx & 7;
            uint32_t so = swz128((uint32_t)(n * 128 + u * 16));
            const char* srcH = (const char*)g_WhiT + n * (CIN * 2) + c * 128 + u * 16;
            const char* srcL = (const char*)g_WloT + n * (CIN * 2) + c * 128 + u * 16;
            *(uint4*)(base + OFF_BHI + so) = *(const uint4*)srcH;
            *(uint4*)(base + OFF_BLO + so) = *(const uint4*)srcL;
        }
        __syncthreads();

        if (c < 3) {
            #pragma unroll
            for (int i = 0; i < 8; i++) {
                int idx = i * 256 + tid;
                int r = idx >> 4, q = idx & 15;
                int node = row0 + r;
                v[i] = (node < NN)
                     ? x4[(size_t)node * (CIN / 4) + (c + 1) * 16 + q]
                     : make_float4(0.f, 0.f, 0.f, 0.f);
            }
        }

        #pragma unroll
        for (int ks = 0; ks < 4; ks++) {
            uint32_t ah[2][4], al[2][4];
            #pragma unroll
            for (int mi = 0; mi < 2; mi++) {
                uint32_t r = (uint32_t)(wm * 32 + mi * 16 + (lane & 15));
                uint32_t kb = (uint32_t)(ks * 32 + (lane >> 4) * 16);
                uint32_t so = swz128(r * 128 + kb);
                ldsm_x4(ah[mi], base_u + OFF_AHI + so);
                ldsm_x4(al[mi], base_u + OFF_ALO + so);
            }
            #pragma unroll
            for (int nj2 = 0; nj2 < 4; nj2++) {
                uint32_t n = (uint32_t)(wn * 64 + nj2 * 16 + (lane & 7)
                                        + ((lane >> 4) << 3));
                uint32_t kb = (uint32_t)(ks * 32 + ((lane >> 3) & 1) * 16);
                uint32_t so = swz128(n * 128 + kb);
                uint32_t bh[4], bl[4];
                ldsm_x4(bh, base_u + OFF_BHI + so);
                ldsm_x4(bl, base_u + OFF_BLO + so);
                #pragma unroll
                for (int mi = 0; mi < 2; mi++) {
                    mma_bf16(acc[mi][nj2 * 2 + 0], ah[mi], bh[0], bh[1]);
                    mma_bf16(acc[mi][nj2 * 2 + 1], ah[mi], bh[2], bh[3]);
                    mma_bf16(acc[mi][nj2 * 2 + 0], ah[mi], bl[0], bl[1]);
                    mma_bf16(acc[mi][nj2 * 2 + 1], ah[mi], bl[2], bl[3]);
                    mma_bf16(acc[mi][nj2 * 2 + 0], al[mi], bh[0], bh[1]);
                    mma_bf16(acc[mi][nj2 * 2 + 1], al[mi], bh[2], bh[3]);
                }
            }
        }
        __syncthreads();
    }

    const int group = lane >> 2;
    const int qp    = lane & 3;
    #pragma unroll
    for (int mi = 0; mi < 2; mi++) {
        #pragma unroll
        for (int half = 0; half < 2; half++) {
            int r = wm * 32 + mi * 16 + half * 8 + group;
            int node = row0 + r;
            if (node < NN) {
                __half* hrow = g_hs16 + (size_t)node * HID;
                #pragma unroll
                for (int nj = 0; nj < 8; nj++) {
                    int col = wn * 64 + nj * 8 + qp * 2;
                    __half2 hh = __floats2half2_rn(
                        acc[mi][nj][half * 2 + 0],
                        acc[mi][nj][half * 2 + 1]);
                    *(__half2*)(hrow + col) = hh;
                }
            }
        }
    }
}

// ---------------------------------------------------------------------------
// Aggregate + final linear + log_softmax.  One warp per dst.
// 8 edges per iteration; each half-warp owns 4 -> 4 independent LDG.128
// in flight per lane (MLP=4). Branch-free tail via zero row NN / coeff 0.
// ---------------------------------------------------------------------------
__global__ __launch_bounds__(256) void k_agg_final(const float* __restrict__ bc,
                                                   const float* __restrict__ Wl,
                                                   const float* __restrict__ bl,
                                                   float* __restrict__ out) {
    __shared__ float sW[HID][COUT + 1];
    __shared__ float sBc[HID];
    __shared__ float sBl[COUT];
    __shared__ float sStage[8][HID];
    for (int i = threadIdx.x; i < HID * COUT; i += 256) {
        int d = i >> 4, c = i & 15;
        sW[d][c] = Wl[i];
    }
    for (int i = threadIdx.x; i < HID; i += 256) sBc[i] = bc[i];
    if (threadIdx.x < COUT) sBl[threadIdx.x] = bl[threadIdx.x];
    __syncthreads();

    const int lane = threadIdx.x & 31;
    const int wblk = threadIdx.x >> 5;
    const int dst  = (blockIdx.x * blockDim.x + threadIdx.x) >> 5;
    if (dst >= NN) return;

    const int s0 = g_off[dst];
    const int s1 = g_off[dst + 1];
    const float di = g_dinv[dst];
    const uint4* hp = (const uint4*)g_hs16;
    const int seg = lane & 15;
    const int hlf = lane >> 4;

    float a0, a1, a2, a3, a4, a5, a6, a7;
    {   // self row: half 0 dst row with coeff di, half 1 zero row
        int ssrc = hlf ? NN : dst;
        float cf = hlf ? 0.f : di;
        uint4 u = __ldg(hp + (size_t)ssrc * 16 + seg);
        float2 f0 = __half22float2(*(__half2*)&u.x);
        float2 f1 = __half22float2(*(__half2*)&u.y);
        float2 f2 = __half22float2(*(__half2*)&u.z);
        float2 f3 = __half22float2(*(__half2*)&u.w);
        a0 = f0.x * cf; a1 = f0.y * cf; a2 = f1.x * cf; a3 = f1.y * cf;
        a4 = f2.x * cf; a5 = f2.y * cf; a6 = f3.x * cf; a7 = f3.y * cf;
    }

    for (int b = s0; b < s1; b += 32) {
        int m = s1 - b; if (m > 32) m = 32;
        int   s  = (lane < m) ? __ldg(g_esrc + b + lane) : NN;
        float ds = (lane < m) ? __ldg(g_dinv + s) : 0.f;
        #pragma unroll 1
        for (int j = 0; j < m; j += 8) {
            // half-warp hlf handles edges j+2t+hlf, t=0..3
            int   e0 = __shfl_sync(0xffffffffu, s,  j + 0 + hlf);
            int   e1 = __shfl_sync(0xffffffffu, s,  j + 2 + hlf);
            int   e2 = __shfl_sync(0xffffffffu, s,  j + 4 + hlf);
            int   e3 = __shfl_sync(0xffffffffu, s,  j + 6 + hlf);
            float c0 = __shfl_sync(0xffffffffu, ds, j + 0 + hlf);
            float c1 = __shfl_sync(0xffffffffu, ds, j + 2 + hlf);
            float c2 = __shfl_sync(0xffffffffu, ds, j + 4 + hlf);
            float c3 = __shfl_sync(0xffffffffu, ds, j + 6 + hlf);
            uint4 u0 = __ldg(hp + (size_t)e0 * 16 + seg);
            uint4 u1 = __ldg(hp + (size_t)e1 * 16 + seg);
            uint4 u2 = __ldg(hp + (size_t)e2 * 16 + seg);
            uint4 u3 = __ldg(hp + (size_t)e3 * 16 + seg);
            {
                float2 f0 = __half22float2(*(__half2*)&u0.x);
                float2 f1 = __half22float2(*(__half2*)&u0.y);
                float2 f2 = __half22float2(*(__half2*)&u0.z);
                float2 f3 = __half22float2(*(__half2*)&u0.w);
                a0 = fmaf(f0.x, c0, a0); a1 = fmaf(f0.y, c0, a1);
                a2 = fmaf(f1.x, c0, a2); a3 = fmaf(f1.y, c0, a3);
                a4 = fmaf(f2.x, c0, a4); a5 = fmaf(f2.y, c0, a5);
                a6 = fmaf(f3.x, c0, a6); a7 = fmaf(f3.y, c0, a7);
            }
            {
                float2 f0 = __half22float2(*(__half2*)&u1.x);
                float2 f1 = __half22float2(*(__half2*)&u1.y);
                float2 f2 = __half22float2(*(__half2*)&u1.z);
                float2 f3 = __half22float2(*(__half2*)&u1.w);
                a0 = fmaf(f0.x, c1, a0); a1 = fmaf(f0.y, c1, a1);
                a2 = fmaf(f1.x, c1, a2); a3 = fmaf(f1.y, c1, a3);
                a4 = fmaf(f2.x, c1, a4); a5 = fmaf(f2.y, c1, a5);
                a6 = fmaf(f3.x, c1, a6); a7 = fmaf(f3.y, c1, a7);
            }
            {
                float2 f0 = __half22float2(*(__half2*)&u2.x);
                float2 f1 = __half22float2(*(__half2*)&u2.y);
                float2 f2 = __half22float2(*(__half2*)&u2.z);
                float2 f3 = __half22float2(*(__half2*)&u2.w);
                a0 = fmaf(f0.x, c2, a0); a1 = fmaf(f0.y, c2, a1);
                a2 = fmaf(f1.x, c2, a2); a3 = fmaf(f1.y, c2, a3);
                a4 = fmaf(f2.x, c2, a4); a5 = fmaf(f2.y, c2, a5);
                a6 = fmaf(f3.x, c2, a6); a7 = fmaf(f3.y, c2, a7);
            }
            {
                float2 f0 = __half22float2(*(__half2*)&u3.x);
                float2 f1 = __half22float2(*(__half2*)&u3.y);
                float2 f2 = __half22float2(*(__half2*)&u3.z);
                float2 f3 = __half22float2(*(__half2*)&u3.w);
                a0 = fmaf(f0.x, c3, a0); a1 = fmaf(f0.y, c3, a1);
                a2 = fmaf(f1.x, c3, a2); a3 = fmaf(f1.y, c3, a3);
                a4 = fmaf(f2.x, c3, a4); a5 = fmaf(f2.y, c3, a5);
                a6 = fmaf(f3.x, c3, a6); a7 = fmaf(f3.y, c3, a7);
            }
        }
    }

    a0 += __shfl_xor_sync(0xffffffffu, a0, 16);
    a1 += __shfl_xor_sync(0xffffffffu, a1, 16);
    a2 += __shfl_xor_sync(0xffffffffu, a2, 16);
    a3 += __shfl_xor_sync(0xffffffffu, a3, 16);
    a4 += __shfl_xor_sync(0xffffffffu, a4, 16);
    a5 += __shfl_xor_sync(0xffffffffu, a5, 16);
    a6 += __shfl_xor_sync(0xffffffffu, a6, 16);
    a7 += __shfl_xor_sync(0xffffffffu, a7, 16);

    if (hlf == 0) {
        float* st = &sStage[wblk][seg * 8];
        st[0] = a0; st[1] = a1; st[2] = a2; st[3] = a3;
        st[4] = a4; st[5] = a5; st[6] = a6; st[7] = a7;
    }
    __syncwarp();

    float na[4];
    #pragma unroll
    for (int t = 0; t < 4; t++) {
        float v = sStage[wblk][lane + 32 * t];
        na[t] = fmaxf(v * di + sBc[lane + 32 * t], 0.f);
    }

    float p[COUT];
    #pragma unroll
    for (int c = 0; c < COUT; c++) {
        p[c] = na[0] * sW[lane][c] + na[1] * sW[lane + 32][c]
             + na[2] * sW[lane + 64][c] + na[3] * sW[lane + 96][c];
    }
    #pragma unroll
    for (int off = 16; off > 0; off >>= 1)
        #pragma unroll
        for (int c = 0; c < COUT; c++)
            p[c] += __shfl_xor_sync(0xffffffffu, p[c], off);

    #pragma unroll
    for (int c = 0; c < COUT; c++) p[c] += sBl[c];

    float mx = p[0];
    #pragma unroll
    for (int c = 1; c < COUT; c++) mx = fmaxf(mx, p[c]);
    float sum = 0.f;
    #pragma unroll
    for (int c = 0; c < COUT; c++) sum += expf(p[c] - mx);
    float lse = mx + logf(sum);

    if (lane < COUT) out[(size_t)dst * COUT + lane] = p[lane] - lse;
}

// ---------------------------------------------------------------------------
extern "C" void kernel_launch(void* const* d_in, const int* in_sizes, int n_in,
                              void* d_out, int out_size) {
    const float* x      = (const float*)d_in[0];
    const void*  eidx   = d_in[1];
    const float* W_conv = (const float*)d_in[2];
    const float* b_conv = (const float*)d_in[3];
    const float* W_lin  = (const float*)d_in[4];
    const float* b_lin  = (const float*)d_in[5];
    float* out = (float*)d_out;

    // one-time handle creation (idempotent; identical launch set every call)
    static cudaStream_t s_side = nullptr;
    static cudaEvent_t  ev_fork = nullptr, ev_join = nullptr;
    if (s_side == nullptr) {
        cudaStreamCreateWithFlags(&s_side, cudaStreamNonBlocking);
        cudaEventCreateWithFlags(&ev_fork, cudaEventDisableTiming);
        cudaEventCreateWithFlags(&ev_join, cudaEventDisableTiming);
        cudaFuncSetAttribute(k_gemm_tc,
                             cudaFuncAttributeMaxDynamicSharedMemorySize,
                             SMEM_DYN);
    }

    k_init<<<(NN + 255) / 256, 256>>>((const int*)eidx, W_conv);

    // fork: edge preprocessing on side stream
    cudaEventRecord(ev_fork, 0);
    cudaStreamWaitEvent(s_side, ev_fork, 0);
    k_deg<<<1024, 256, 0, s_side>>>(eidx);
    k_scanA<<<NBLK, 1024, 0, s_side>>>();
    k_scanB<<<1, 128, 0, s_side>>>();
    k_scanC<<<(NN + 255) / 256, 256, 0, s_side>>>();
    k_sort<<<1024, 256, 0, s_side>>>(eidx);
    cudaEventRecord(ev_join, s_side);

    // main stream: GEMM runs concurrently with preprocessing
    k_gemm_tc<<<(NN + 127) / 128, 256, SMEM_DYN>>>(x);

    // join, then aggregate + final
    cudaStreamWaitEvent(0, ev_join, 0);
    k_agg_final<<<(NN * 32 + 255) / 256, 256>>>(b_conv, W_lin, b_lin, out);
}

// round 9
// speedup vs baseline: 1.7263x; 1.0943x over previous
#include <cuda_runtime.h>
#include <cuda_bf16.h>
#include <cuda_fp16.h>
#include <math.h>
#include <stdint.h>

#define NN   100000
#define NE   1600000
#define CIN  256
#define HID  128
#define COUT 16
#define NBLK 98          // ceil(NN/1024)

// ---------------- scratch (__device__ globals; no allocs allowed) ----------
__device__ __half          g_hs16[(size_t)(NN + 1) * HID]; // raw h, +1 zero row
__device__ int             g_deg[NN];
__device__ float           g_dinv[NN];
__device__ int             g_psc[NN];
__device__ int             g_off[NN + 1];
__device__ int             g_wptr[NN];
__device__ int             g_bsum[NBLK];
__device__ int             g_boff[NBLK];
__device__ int             g_esrc[NE];
__device__ int             g_is64;
__device__ __nv_bfloat16   g_WT[HID * CIN];   // W^T bf16 [n][k]

__device__ __forceinline__ uint32_t smem_u32(const void* p) {
    uint32_t a;
    asm("{ .reg .u64 t; cvta.to.shared.u64 t, %1; cvt.u32.u64 %0, t; }"
        : "=r"(a) : "l"(p));
    return a;
}
__device__ __forceinline__ uint32_t swz128(uint32_t off) {
    return off ^ ((off >> 3) & 0x70);
}
__device__ __forceinline__ void ldsm_x4(uint32_t* r, uint32_t addr) {
    asm volatile("ldmatrix.sync.aligned.m8n8.x4.shared.b16 {%0,%1,%2,%3}, [%4];"
                 : "=r"(r[0]), "=r"(r[1]), "=r"(r[2]), "=r"(r[3]) : "r"(addr));
}
__device__ __forceinline__ void mma_bf16(float* d, const uint32_t* a,
                                         uint32_t b0, uint32_t b1) {
    asm volatile("mma.sync.aligned.m16n8k16.row.col.f32.bf16.bf16.f32 "
                 "{%0,%1,%2,%3}, {%4,%5,%6,%7}, {%8,%9}, {%0,%1,%2,%3};"
                 : "+f"(d[0]), "+f"(d[1]), "+f"(d[2]), "+f"(d[3])
                 : "r"(a[0]), "r"(a[1]), "r"(a[2]), "r"(a[3]), "r"(b0), "r"(b1));
}
__device__ __forceinline__ uint32_t cvt_bf16x2(float hi, float lo) {
    uint32_t r;
    asm("cvt.rn.bf16x2.f32 %0, %1, %2;" : "=r"(r) : "f"(hi), "f"(lo));
    return r;
}

// ---------------------------------------------------------------------------
// K0 (fused): zero degrees, sniff dtype, W -> bf16 W^T, zero hs16 row NN
// ---------------------------------------------------------------------------
__global__ void k_init(const int* __restrict__ e32, const float* __restrict__ W) {
    int i = blockIdx.x * blockDim.x + threadIdx.x;
    if (i < NN) g_deg[i] = 0;
    if (i < CIN * HID) {
        int k = i >> 7, n = i & 127;
        g_WT[n * CIN + k] = __float2bfloat16_rn(W[i]);
    }
    if (i < 16)
        ((uint4*)(g_hs16 + (size_t)NN * HID))[i] = make_uint4(0u, 0u, 0u, 0u);
    if (i == 0) {
        int is64 = 1;
        #pragma unroll 1
        for (int j = 0; j < 64; j++)
            if (e32[2 * j + 1] != 0) { is64 = 0; break; }
        g_is64 = is64;
    }
}

__global__ void k_deg(const void* __restrict__ eptr) {
    const long long* e64 = (const long long*)eptr;
    const int*       e32 = (const int*)eptr;
    const int is64 = g_is64;
    for (int e = blockIdx.x * blockDim.x + threadIdx.x; e < NE;
         e += gridDim.x * blockDim.x) {
        int d = is64 ? (int)e64[NE + e] : e32[NE + e];
        atomicAdd(&g_deg[d], 1);
    }
}

__global__ __launch_bounds__(1024) void k_scanA() {
    __shared__ int ss[1024];
    const int t = threadIdx.x;
    const int i = blockIdx.x * 1024 + t;
    int v = (i < NN) ? g_deg[i] : 0;
    ss[t] = v;
    __syncthreads();
    #pragma unroll
    for (int off = 1; off < 1024; off <<= 1) {
        int add = (t >= off) ? ss[t - off] : 0;
        __syncthreads();
        ss[t] += add;
        __syncthreads();
    }
    if (i < NN) g_psc[i] = ss[t] - v;
    if (t == 1023) g_bsum[blockIdx.x] = ss[1023];
}

__global__ __launch_bounds__(128) void k_scanB() {
    __shared__ int warp_tot[4];
    const int t = threadIdx.x;
    const int lane = t & 31, w = t >> 5;
    int v = (t < NBLK) ? g_bsum[t] : 0;
    int inc = v;
    #pragma unroll
    for (int off = 1; off < 32; off <<= 1) {
        int up = __shfl_up_sync(0xffffffffu, inc, off);
        if (lane >= off) inc += up;
    }
    if (lane == 31) warp_tot[w] = inc;
    __syncthreads();
    int pre = 0;
    #pragma unroll
    for (int j = 0; j < 4; j++) pre += (j < w) ? warp_tot[j] : 0;
    if (t < NBLK) g_boff[t] = pre + inc - v;
    if (t == 127) g_off[NN] = pre + inc;
}

__global__ void k_scanC() {
    int i = blockIdx.x * blockDim.x + threadIdx.x;
    if (i < NN) {
        int o = g_psc[i] + g_boff[i >> 10];
        g_off[i]  = o;
        g_wptr[i] = o;
        g_dinv[i] = rsqrtf((float)(g_deg[i] + 1));
    }
}

__global__ void k_sort(const void* __restrict__ eptr) {
    const long long* e64 = (const long long*)eptr;
    const int*       e32 = (const int*)eptr;
    const int is64 = g_is64;
    for (int e = blockIdx.x * blockDim.x + threadIdx.x; e < NE;
         e += gridDim.x * blockDim.x) {
        int s = is64 ? (int)e64[e]      : e32[e];
        int d = is64 ? (int)e64[NE + e] : e32[NE + e];
        int pos = atomicAdd(&g_wptr[d], 1);
        g_esrc[pos] = s;
    }
}

// ---------------------------------------------------------------------------
// GEMM: h = x @ W_conv, single-pass bf16 mma.sync, fp32 accum.
// CTA tile 128x128, K chunks of 64. Stores RAW h (fp16).
// ---------------------------------------------------------------------------
#define TILE_B   16384
#define OFF_A    0
#define OFF_B    16384
#define SMEM_DYN (2 * TILE_B + 256)

__global__ __launch_bounds__(256, 2) void k_gemm_tc(const float* __restrict__ x) {
    extern __shared__ char dsm_raw[];
    char* const base = (char*)(((uintptr_t)dsm_raw + 127) & ~(uintptr_t)127);
    const uint32_t base_u = smem_u32(base);

    const int tid  = threadIdx.x;
    const int lane = tid & 31;
    const int wid  = tid >> 5;
    const int wm   = wid & 3;
    const int wn   = wid >> 2;
    const int row0 = blockIdx.x * 128;

    float acc[2][8][4];
    #pragma unroll
    for (int i = 0; i < 2; i++)
        #pragma unroll
        for (int j = 0; j < 8; j++)
            #pragma unroll
            for (int q = 0; q < 4; q++) acc[i][j][q] = 0.f;

    const float4* x4 = (const float4*)x;

    float4 v[8];
    #pragma unroll
    for (int i = 0; i < 8; i++) {
        int idx = i * 256 + tid;
        int r = idx >> 4, q = idx & 15;
        int node = row0 + r;
        v[i] = (node < NN) ? x4[(size_t)node * (CIN / 4) + q]
                           : make_float4(0.f, 0.f, 0.f, 0.f);
    }

    for (int c = 0; c < 4; c++) {
        // convert prefetched x chunk -> bf16 (RN) into smem A (SW128)
        #pragma unroll
        for (int i = 0; i < 8; i++) {
            int idx = i * 256 + tid;
            int r = idx >> 4, q = idx & 15;
            float4 w = v[i];
            uint32_t h01 = cvt_bf16x2(w.y, w.x);
            uint32_t h23 = cvt_bf16x2(w.w, w.z);
            uint32_t so = swz128((uint32_t)(r * 128 + q * 8));
            *(uint2*)(base + OFF_A + so) = make_uint2(h01, h23);
        }
        // W^T chunk -> smem B
        #pragma unroll
        for (int i = 0; i < 4; i++) {
            int idx = i * 256 + tid;
            int n = idx >> 3, u = idx & 7;
            uint32_t so = swz128((uint32_t)(n * 128 + u * 16));
            const char* src = (const char*)g_WT + n * (CIN * 2) + c * 128 + u * 16;
            *(uint4*)(base + OFF_B + so) = *(const uint4*)src;
        }
        __syncthreads();

        if (c < 3) {
            #pragma unroll
            for (int i = 0; i < 8; i++) {
                int idx = i * 256 + tid;
                int r = idx >> 4, q = idx & 15;
                int node = row0 + r;
                v[i] = (node < NN)
                     ? x4[(size_t)node * (CIN / 4) + (c + 1) * 16 + q]
                     : make_float4(0.f, 0.f, 0.f, 0.f);
            }
        }

        #pragma unroll
        for (int ks = 0; ks < 4; ks++) {
            uint32_t ah[2][4];
            #pragma unroll
            for (int mi = 0; mi < 2; mi++) {
                uint32_t r = (uint32_t)(wm * 32 + mi * 16 + (lane & 15));
                uint32_t kb = (uint32_t)(ks * 32 + (lane >> 4) * 16);
                ldsm_x4(ah[mi], base_u + OFF_A + swz128(r * 128 + kb));
            }
            #pragma unroll
            for (int nj2 = 0; nj2 < 4; nj2++) {
                uint32_t n = (uint32_t)(wn * 64 + nj2 * 16 + (lane & 7)
                                        + ((lane >> 4) << 3));
                uint32_t kb = (uint32_t)(ks * 32 + ((lane >> 3) & 1) * 16);
                uint32_t bh[4];
                ldsm_x4(bh, base_u + OFF_B + swz128(n * 128 + kb));
                #pragma unroll
                for (int mi = 0; mi < 2; mi++) {
                    mma_bf16(acc[mi][nj2 * 2 + 0], ah[mi], bh[0], bh[1]);
                    mma_bf16(acc[mi][nj2 * 2 + 1], ah[mi], bh[2], bh[3]);
                }
            }
        }
        __syncthreads();
    }

    const int group = lane >> 2;
    const int qp    = lane & 3;
    #pragma unroll
    for (int mi = 0; mi < 2; mi++) {
        #pragma unroll
        for (int half = 0; half < 2; half++) {
            int r = wm * 32 + mi * 16 + half * 8 + group;
            int node = row0 + r;
            if (node < NN) {
                __half* hrow = g_hs16 + (size_t)node * HID;
                #pragma unroll
                for (int nj = 0; nj < 8; nj++) {
                    int col = wn * 64 + nj * 8 + qp * 2;
                    __half2 hh = __floats2half2_rn(
                        acc[mi][nj][half * 2 + 0],
                        acc[mi][nj][half * 2 + 1]);
                    *(__half2*)(hrow + col) = hh;
                }
            }
        }
    }
}

// ---------------------------------------------------------------------------
// Aggregate + final linear + log_softmax.  One warp per dst.
// ---------------------------------------------------------------------------
__global__ __launch_bounds__(256) void k_agg_final(const float* __restrict__ bc,
                                                   const float* __restrict__ Wl,
                                                   const float* __restrict__ bl,
                                                   float* __restrict__ out) {
    __shared__ float sW[HID][COUT + 1];
    __shared__ float sBc[HID];
    __shared__ float sBl[COUT];
    __shared__ float sStage[8][HID];
    for (int i = threadIdx.x; i < HID * COUT; i += 256) {
        int d = i >> 4, c = i & 15;
        sW[d][c] = Wl[i];
    }
    for (int i = threadIdx.x; i < HID; i += 256) sBc[i] = bc[i];
    if (threadIdx.x < COUT) sBl[threadIdx.x] = bl[threadIdx.x];
    __syncthreads();

    const int lane = threadIdx.x & 31;
    const int wblk = threadIdx.x >> 5;
    const int dst  = (blockIdx.x * blockDim.x + threadIdx.x) >> 5;
    if (dst >= NN) return;

    const int s0 = g_off[dst];
    const int s1 = g_off[dst + 1];
    const float di = g_dinv[dst];
    const uint4* hp = (const uint4*)g_hs16;
    const int seg = lane & 15;
    const int hlf = lane >> 4;

    float a0, a1, a2, a3, a4, a5, a6, a7;
    {
        int ssrc = hlf ? NN : dst;
        float cf = hlf ? 0.f : di;
        uint4 u = __ldg(hp + (size_t)ssrc * 16 + seg);
        float2 f0 = __half22float2(*(__half2*)&u.x);
        float2 f1 = __half22float2(*(__half2*)&u.y);
        float2 f2 = __half22float2(*(__half2*)&u.z);
        float2 f3 = __half22float2(*(__half2*)&u.w);
        a0 = f0.x * cf; a1 = f0.y * cf; a2 = f1.x * cf; a3 = f1.y * cf;
        a4 = f2.x * cf; a5 = f2.y * cf; a6 = f3.x * cf; a7 = f3.y * cf;
    }

    for (int b = s0; b < s1; b += 32) {
        int m = s1 - b; if (m > 32) m = 32;
        int   s  = (lane < m) ? __ldg(g_esrc + b + lane) : NN;
        float ds = (lane < m) ? __ldg(g_dinv + s) : 0.f;
        #pragma unroll 1
        for (int j = 0; j < m; j += 8) {
            int   e0 = __shfl_sync(0xffffffffu, s,  j + 0 + hlf);
            int   e1 = __shfl_sync(0xffffffffu, s,  j + 2 + hlf);
            int   e2 = __shfl_sync(0xffffffffu, s,  j + 4 + hlf);
            int   e3 = __shfl_sync(0xffffffffu, s,  j + 6 + hlf);
            float c0 = __shfl_sync(0xffffffffu, ds, j + 0 + hlf);
            float c1 = __shfl_sync(0xffffffffu, ds, j + 2 + hlf);
            float c2 = __shfl_sync(0xffffffffu, ds, j + 4 + hlf);
            float c3 = __shfl_sync(0xffffffffu, ds, j + 6 + hlf);
            uint4 u0 = __ldg(hp + (size_t)e0 * 16 + seg);
            uint4 u1 = __ldg(hp + (size_t)e1 * 16 + seg);
            uint4 u2 = __ldg(hp + (size_t)e2 * 16 + seg);
            uint4 u3 = __ldg(hp + (size_t)e3 * 16 + seg);
            {
                float2 f0 = __half22float2(*(__half2*)&u0.x);
                float2 f1 = __half22float2(*(__half2*)&u0.y);
                float2 f2 = __half22float2(*(__half2*)&u0.z);
                float2 f3 = __half22float2(*(__half2*)&u0.w);
                a0 = fmaf(f0.x, c0, a0); a1 = fmaf(f0.y, c0, a1);
                a2 = fmaf(f1.x, c0, a2); a3 = fmaf(f1.y, c0, a3);
                a4 = fmaf(f2.x, c0, a4); a5 = fmaf(f2.y, c0, a5);
                a6 = fmaf(f3.x, c0, a6); a7 = fmaf(f3.y, c0, a7);
            }
            {
                float2 f0 = __half22float2(*(__half2*)&u1.x);
                float2 f1 = __half22float2(*(__half2*)&u1.y);
                float2 f2 = __half22float2(*(__half2*)&u1.z);
                float2 f3 = __half22float2(*(__half2*)&u1.w);
                a0 = fmaf(f0.x, c1, a0); a1 = fmaf(f0.y, c1, a1);
                a2 = fmaf(f1.x, c1, a2); a3 = fmaf(f1.y, c1, a3);
                a4 = fmaf(f2.x, c1, a4); a5 = fmaf(f2.y, c1, a5);
                a6 = fmaf(f3.x, c1, a6); a7 = fmaf(f3.y, c1, a7);
            }
            {
                float2 f0 = __half22float2(*(__half2*)&u2.x);
                float2 f1 = __half22float2(*(__half2*)&u2.y);
                float2 f2 = __half22float2(*(__half2*)&u2.z);
                float2 f3 = __half22float2(*(__half2*)&u2.w);
                a0 = fmaf(f0.x, c2, a0); a1 = fmaf(f0.y, c2, a1);
                a2 = fmaf(f1.x, c2, a2); a3 = fmaf(f1.y, c2, a3);
                a4 = fmaf(f2.x, c2, a4); a5 = fmaf(f2.y, c2, a5);
                a6 = fmaf(f3.x, c2, a6); a7 = fmaf(f3.y, c2, a7);
            }
            {
                float2 f0 = __half22float2(*(__half2*)&u3.x);
                float2 f1 = __half22float2(*(__half2*)&u3.y);
                float2 f2 = __half22float2(*(__half2*)&u3.z);
                float2 f3 = __half22float2(*(__half2*)&u3.w);
                a0 = fmaf(f0.x, c3, a0); a1 = fmaf(f0.y, c3, a1);
                a2 = fmaf(f1.x, c3, a2); a3 = fmaf(f1.y, c3, a3);
                a4 = fmaf(f2.x, c3, a4); a5 = fmaf(f2.y, c3, a5);
                a6 = fmaf(f3.x, c3, a6); a7 = fmaf(f3.y, c3, a7);
            }
        }
    }

    a0 += __shfl_xor_sync(0xffffffffu, a0, 16);
    a1 += __shfl_xor_sync(0xffffffffu, a1, 16);
    a2 += __shfl_xor_sync(0xffffffffu, a2, 16);
    a3 += __shfl_xor_sync(0xffffffffu, a3, 16);
    a4 += __shfl_xor_sync(0xffffffffu, a4, 16);
    a5 += __shfl_xor_sync(0xffffffffu, a5, 16);
    a6 += __shfl_xor_sync(0xffffffffu, a6, 16);
    a7 += __shfl_xor_sync(0xffffffffu, a7, 16);

    if (hlf == 0) {
        float* st = &sStage[wblk][seg * 8];
        st[0] = a0; st[1] = a1; st[2] = a2; st[3] = a3;
        st[4] = a4; st[5] = a5; st[6] = a6; st[7] = a7;
    }
    __syncwarp();

    float na[4];
    #pragma unroll
    for (int t = 0; t < 4; t++) {
        float v = sStage[wblk][lane + 32 * t];
        na[t] = fmaxf(v * di + sBc[lane + 32 * t], 0.f);
    }

    float p[COUT];
    #pragma unroll
    for (int c = 0; c < COUT; c++) {
        p[c] = na[0] * sW[lane][c] + na[1] * sW[lane + 32][c]
             + na[2] * sW[lane + 64][c] + na[3] * sW[lane + 96][c];
    }
    #pragma unroll
    for (int off = 16; off > 0; off >>= 1)
        #pragma unroll
        for (int c = 0; c < COUT; c++)
            p[c] += __shfl_xor_sync(0xffffffffu, p[c], off);

    #pragma unroll
    for (int c = 0; c < COUT; c++) p[c] += sBl[c];

    float mx = p[0];
    #pragma unroll
    for (int c = 1; c < COUT; c++) mx = fmaxf(mx, p[c]);
    float sum = 0.f;
    #pragma unroll
    for (int c = 0; c < COUT; c++) sum += expf(p[c] - mx);
    float lse = mx + logf(sum);

    if (lane < COUT) out[(size_t)dst * COUT + lane] = p[lane] - lse;
}

// ---------------------------------------------------------------------------
extern "C" void kernel_launch(void* const* d_in, const int* in_sizes, int n_in,
                              void* d_out, int out_size) {
    const float* x      = (const float*)d_in[0];
    const void*  eidx   = d_in[1];
    const float* W_conv = (const float*)d_in[2];
    const float* b_conv = (const float*)d_in[3];
    const float* W_lin  = (const float*)d_in[4];
    const float* b_lin  = (const float*)d_in[5];
    float* out = (float*)d_out;

    static cudaStream_t s_side = nullptr;
    static cudaEvent_t  ev_fork = nullptr, ev_join = nullptr;
    if (s_side == nullptr) {
        cudaStreamCreateWithFlags(&s_side, cudaStreamNonBlocking);
        cudaEventCreateWithFlags(&ev_fork, cudaEventDisableTiming);
        cudaEventCreateWithFlags(&ev_join, cudaEventDisableTiming);
        cudaFuncSetAttribute(k_gemm_tc,
                             cudaFuncAttributeMaxDynamicSharedMemorySize,
                             SMEM_DYN);
    }

    k_init<<<(NN + 255) / 256, 256>>>((const int*)eidx, W_conv);

    cudaEventRecord(ev_fork, 0);
    cudaStreamWaitEvent(s_side, ev_fork, 0);
    k_deg<<<1024, 256, 0, s_side>>>(eidx);
    k_scanA<<<NBLK, 1024, 0, s_side>>>();
    k_scanB<<<1, 128, 0, s_side>>>();
    k_scanC<<<(NN + 255) / 256, 256, 0, s_side>>>();
    k_sort<<<1024, 256, 0, s_side>>>(eidx);
    cudaEventRecord(ev_join, s_side);

    k_gemm_tc<<<(NN + 127) / 128, 256, SMEM_DYN>>>(x);

    cudaStreamWaitEvent(0, ev_join, 0);
    k_agg_final<<<(NN * 32 + 255) / 256, 256>>>(b_conv, W_lin, b_lin, out);
}